// round 2
// baseline (speedup 1.0000x reference)
#include <cuda_runtime.h>
#include <cstdint>

#define NMAX 100000
#define DH   128
#define BM   64
#define APITCH 132   // padded A-tile pitch (floats) to dodge smem bank conflicts

// ---------------- scratch (static device globals; no allocation) ----------------
__device__ int   g_deg[8 * NMAX];                       // 3.2 MB
__device__ float g_rs [8 * NMAX];                       // 3.2 MB
__device__ float g_agg[4 * (size_t)NMAX * DH];          // 204.8 MB
__device__ float g_h  [2 * (size_t)NMAX * DH];          // 102.4 MB

// ---------------- degree count ----------------
__global__ void deg_kernel(const int* __restrict__ idx, int* __restrict__ deg, int nE) {
    int i = blockIdx.x * blockDim.x + threadIdx.x;
    if (i < nE) atomicAdd(&deg[idx[i]], 1);
}

__global__ void rs_kernel(const int* __restrict__ deg, float* __restrict__ rs, int n) {
    int i = blockIdx.x * blockDim.x + threadIdx.x;
    if (i < n) rs[i] = rsqrtf(fmaxf((float)deg[i], 1.0f));
}

// ---------------- edge aggregation: agg[dst] += x[src] * rs_out[src] ----------------
// one warp per edge; float4 per lane; scalar index loads on lane 0, broadcast;
// vectorized red.global for the scatter-add (no return trip)
__global__ __launch_bounds__(256)
void agg_kernel(const float* __restrict__ x, const float* __restrict__ rs_out,
                const int* __restrict__ src, const int* __restrict__ dst,
                float* __restrict__ agg, int nE) {
    int w    = (int)((blockIdx.x * blockDim.x + threadIdx.x) >> 5);
    int lane = threadIdx.x & 31;
    if (w >= nE) return;
    int s = 0, d = 0; float sc = 0.f;
    if (lane == 0) {
        s  = __ldg(src + w);
        d  = __ldg(dst + w);
        sc = __ldg(rs_out + s);
    }
    s  = __shfl_sync(0xffffffffu, s,  0);
    d  = __shfl_sync(0xffffffffu, d,  0);
    sc = __shfl_sync(0xffffffffu, sc, 0);
    float4 v = __ldg((const float4*)(x + (size_t)s * DH) + lane);
    v.x *= sc; v.y *= sc; v.z *= sc; v.w *= sc;
    float* p = agg + (size_t)d * DH + lane * 4;
    asm volatile("red.global.add.v4.f32 [%0], {%1,%2,%3,%4};"
                 :: "l"(p), "f"(v.x), "f"(v.y), "f"(v.z), "f"(v.w) : "memory");
}

// ---------------- fused pair-GEMM ----------------
// out = maybe_relu((A0 .* rs0) @ W0 + b0) + maybe_relu((A1 .* rs1) @ W1 + b1)
// block: 256 threads, 64-row tile x 128 cols; each thread 4 rows x 8 cols.
extern __shared__ float s_mem[];

__global__ __launch_bounds__(256, 2)
void gemm_pair_kernel(const float* __restrict__ A0, const float* __restrict__ rs0,
                      const float* __restrict__ W0, const float* __restrict__ b0,
                      const float* __restrict__ A1, const float* __restrict__ rs1,
                      const float* __restrict__ W1, const float* __restrict__ b1,
                      float* __restrict__ out, int nrows, int act) {
    float* Ws = s_mem;               // 128*128 floats = 64 KB
    float* As = s_mem + DH * DH;     // 64*132 floats  = 33.8 KB

    int tid = threadIdx.x;
    int tx = tid & 15;               // col group (8 cols each)
    int ty = tid >> 4;               // row group (4 rows each)
    int row0 = blockIdx.x * BM;

    float accF[4][8];
#pragma unroll
    for (int r = 0; r < 4; r++)
#pragma unroll
        for (int c = 0; c < 8; c++) accF[r][c] = 0.f;

#pragma unroll 1
    for (int pass = 0; pass < 2; pass++) {
        const float* A  = pass ? A1 : A0;
        const float* W  = pass ? W1 : W0;
        const float* bb = pass ? b1 : b0;
        const float* rs = pass ? rs1 : rs0;

        __syncthreads();   // protect smem reuse across passes
        // stage W (128x128)
        {
            const float4* Wv  = (const float4*)W;
            float4*       Wsv = (float4*)Ws;
#pragma unroll
            for (int i = 0; i < 16; i++) Wsv[tid + i * 256] = __ldg(Wv + tid + i * 256);
        }
        // stage A tile (64x128), row-scaled by rs
#pragma unroll
        for (int i = 0; i < 8; i++) {
            int idx = tid + i * 256;        // 0..2047 float4 slots
            int r   = idx >> 5;             // tile row
            int c4  = idx & 31;             // float4 col
            int grow = row0 + r;
            float4 v = make_float4(0.f, 0.f, 0.f, 0.f);
            if (grow < nrows) {
                v = __ldg((const float4*)(A + (size_t)grow * DH) + c4);
                float s = __ldg(rs + grow);
                v.x *= s; v.y *= s; v.z *= s; v.w *= s;
            }
            *((float4*)(As + r * APITCH) + c4) = v;
        }
        __syncthreads();

        float accP[4][8];
#pragma unroll
        for (int r = 0; r < 4; r++)
#pragma unroll
            for (int c = 0; c < 8; c++) accP[r][c] = 0.f;

#pragma unroll 2
        for (int k = 0; k < DH; k += 4) {
            float4 a[4];
#pragma unroll
            for (int r = 0; r < 4; r++)
                a[r] = *(const float4*)(As + (4 * ty + r) * APITCH + k);
#pragma unroll
            for (int kk = 0; kk < 4; kk++) {
                float4 w0 = *(const float4*)(Ws + (k + kk) * DH + tx * 8);
                float4 w1 = *(const float4*)(Ws + (k + kk) * DH + tx * 8 + 4);
#pragma unroll
                for (int r = 0; r < 4; r++) {
                    float av = (kk == 0) ? a[r].x : (kk == 1) ? a[r].y : (kk == 2) ? a[r].z : a[r].w;
                    accP[r][0] += av * w0.x;
                    accP[r][1] += av * w0.y;
                    accP[r][2] += av * w0.z;
                    accP[r][3] += av * w0.w;
                    accP[r][4] += av * w1.x;
                    accP[r][5] += av * w1.y;
                    accP[r][6] += av * w1.z;
                    accP[r][7] += av * w1.w;
                }
            }
        }

        float bl[8];
#pragma unroll
        for (int c = 0; c < 8; c++) bl[c] = __ldg(bb + tx * 8 + c);
#pragma unroll
        for (int r = 0; r < 4; r++)
#pragma unroll
            for (int c = 0; c < 8; c++) {
                float v = accP[r][c] + bl[c];
                if (act) v = fmaxf(v, 0.f);
                accF[r][c] += v;
            }
    }

#pragma unroll
    for (int r = 0; r < 4; r++) {
        int grow = row0 + 4 * ty + r;
        if (grow < nrows) {
            float4 o0 = make_float4(accF[r][0], accF[r][1], accF[r][2], accF[r][3]);
            float4 o1 = make_float4(accF[r][4], accF[r][5], accF[r][6], accF[r][7]);
            *((float4*)(out + (size_t)grow * DH + tx * 8))     = o0;
            *((float4*)(out + (size_t)grow * DH + tx * 8 + 4)) = o1;
        }
    }
}

// ---------------- LayerNorm, in place, warp per row ----------------
// rows [0, nA) use gamma/beta at +0; rows [nA, nTot) use +DH
__global__ __launch_bounds__(256)
void ln_kernel(float* __restrict__ data, const float* __restrict__ g0,
               const float* __restrict__ b0, int nA, int nTot) {
    int w    = (int)((blockIdx.x * blockDim.x + threadIdx.x) >> 5);
    int lane = threadIdx.x & 31;
    if (w >= nTot) return;
    int off = (w < nA) ? 0 : DH;
    float* row = data + (size_t)w * DH;
    float4 v = ((const float4*)row)[lane];
    float s  = v.x + v.y + v.z + v.w;
    float sq = v.x * v.x + v.y * v.y + v.z * v.z + v.w * v.w;
#pragma unroll
    for (int o = 16; o > 0; o >>= 1) {
        s  += __shfl_xor_sync(0xffffffffu, s, o);
        sq += __shfl_xor_sync(0xffffffffu, sq, o);
    }
    float mean = s * (1.f / 128.f);
    float var  = sq * (1.f / 128.f) - mean * mean;
    float inv  = rsqrtf(var + 1e-5f);
    float4 g = __ldg((const float4*)(g0 + off) + lane);
    float4 b = __ldg((const float4*)(b0 + off) + lane);
    float4 o;
    o.x = (v.x - mean) * inv * g.x + b.x;
    o.y = (v.y - mean) * inv * g.y + b.y;
    o.z = (v.z - mean) * inv * g.z + b.z;
    o.w = (v.w - mean) * inv * g.w + b.w;
    ((float4*)row)[lane] = o;
}

// ---------------- host orchestration ----------------
extern "C" void kernel_launch(void* const* d_in, const int* in_sizes, int n_in,
                              void* d_out, int out_size) {
    const float* x_A  = (const float*)d_in[0];
    const float* x_B  = (const float*)d_in[1];
    const float* W0   = (const float*)d_in[2];
    const float* b0   = (const float*)d_in[3];
    const float* W1   = (const float*)d_in[4];
    const float* b1   = (const float*)d_in[5];
    const float* ln_g = (const float*)d_in[6];
    const float* ln_b = (const float*)d_in[7];
    const int* eidx[8];
    int        esz[8];
    for (int i = 0; i < 8; i++) { eidx[i] = (const int*)d_in[8 + i]; esz[i] = in_sizes[8 + i]; }
    // eidx order: src_aa, dst_aa, src_ab, dst_ab, src_ba, dst_ba, src_bb, dst_bb

    const int N  = in_sizes[0] / DH;
    const int DD = DH * DH;
    float* out = (float*)d_out;

    int*   deg; float* rs; float* agg; float* h;
    cudaGetSymbolAddress((void**)&deg, g_deg);
    cudaGetSymbolAddress((void**)&rs,  g_rs);
    cudaGetSymbolAddress((void**)&agg, g_agg);
    cudaGetSymbolAddress((void**)&h,   g_h);

    const size_t ND = (size_t)N * DH;
    float* aggp[4] = { agg, agg + ND, agg + 2 * ND, agg + 3 * ND };

    const int smem_bytes = (DH * DH + BM * APITCH) * 4;
    cudaFuncSetAttribute(gemm_pair_kernel, cudaFuncAttributeMaxDynamicSharedMemorySize, smem_bytes);

    // ---- degrees (shared by both layers) ----
    cudaMemsetAsync(deg, 0, 8 * (size_t)N * sizeof(int));
    for (int j = 0; j < 8; j++)
        deg_kernel<<<(esz[j] + 255) / 256, 256>>>(eidx[j], deg + (size_t)j * N, esz[j]);
    rs_kernel<<<(8 * N + 255) / 256, 256>>>(deg, rs, 8 * N);
    // rs layout: rs_out[e] = rs + 2e*N ; rs_in[e] = rs + (2e+1)*N

    const int gemm_blocks = (N + BM - 1) / BM;

    // =================== layer 0 ===================
    cudaMemsetAsync(agg, 0, 4 * ND * sizeof(float));
    {
        const float* xsrc[4] = { x_A, x_A, x_B, x_B };   // etype 0:aa 1:ab 2:ba 3:bb
        for (int e = 0; e < 4; e++) {
            int nE = esz[2 * e];
            int blocks = (nE * 32 + 255) / 256;
            agg_kernel<<<blocks, 256>>>(xsrc[e], rs + (size_t)(2 * e) * N,
                                        eidx[2 * e], eidx[2 * e + 1], aggp[e], nE);
        }
    }
    // dst A: etypes aa(0) + ba(2);  dst B: ab(1) + bb(3)
    gemm_pair_kernel<<<gemm_blocks, 256, smem_bytes>>>(
        aggp[0], rs + 1 * (size_t)N, W0 + 0 * DD, b0 + 0 * DH,
        aggp[2], rs + 5 * (size_t)N, W0 + 2 * DD, b0 + 2 * DH,
        h, N, /*act=*/1);
    gemm_pair_kernel<<<gemm_blocks, 256, smem_bytes>>>(
        aggp[1], rs + 3 * (size_t)N, W0 + 1 * DD, b0 + 1 * DH,
        aggp[3], rs + 7 * (size_t)N, W0 + 3 * DD, b0 + 3 * DH,
        h + ND, N, /*act=*/1);
    ln_kernel<<<(2 * N + 7) / 8, 256>>>(h, ln_g + 0, ln_b + 0, N, 2 * N);

    // =================== layer 1 ===================
    cudaMemsetAsync(agg, 0, 4 * ND * sizeof(float));
    {
        const float* hsrc[4] = { h, h, h + ND, h + ND };
        for (int e = 0; e < 4; e++) {
            int nE = esz[2 * e];
            int blocks = (nE * 32 + 255) / 256;
            agg_kernel<<<blocks, 256>>>(hsrc[e], rs + (size_t)(2 * e) * N,
                                        eidx[2 * e], eidx[2 * e + 1], aggp[e], nE);
        }
    }
    gemm_pair_kernel<<<gemm_blocks, 256, smem_bytes>>>(
        aggp[0], rs + 1 * (size_t)N, W1 + 0 * DD, b1 + 0 * DH,
        aggp[2], rs + 5 * (size_t)N, W1 + 2 * DD, b1 + 2 * DH,
        out, N, /*act=*/0);
    gemm_pair_kernel<<<gemm_blocks, 256, smem_bytes>>>(
        aggp[1], rs + 3 * (size_t)N, W1 + 1 * DD, b1 + 1 * DH,
        aggp[3], rs + 7 * (size_t)N, W1 + 3 * DD, b1 + 3 * DH,
        out + ND, N, /*act=*/0);
    ln_kernel<<<(2 * N + 7) / 8, 256>>>(out, ln_g + 2 * DH, ln_b + 2 * DH, N, 2 * N);
}

// round 3
// speedup vs baseline: 1.5215x; 1.5215x over previous
#include <cuda_runtime.h>
#include <cstdint>

#define NMAX 100000
#define EMAX 1600000
#define DH   128
#define BM   64
#define APITCH 132   // padded A-tile pitch (floats)

typedef unsigned long long u64t;

#define FMA2(d, a, b, c) \
    asm("fma.rn.f32x2 %0, %1, %2, %3;" : "=l"(d) : "l"(a), "l"(b), "l"(c))
#define PACK_DUP(d, f) \
    asm("mov.b64 %0, {%1, %1};" : "=l"(d) : "f"(f))
#define UNPACK2(lo, hi, v) \
    asm("mov.b64 {%0, %1}, %2;" : "=f"(lo), "=f"(hi) : "l"(v))

// ---------------- scratch (static device globals; no allocation) ----------------
__device__ int   g_deg[8 * NMAX];                       // 3.2 MB
__device__ float g_rs [8 * NMAX];                       // 3.2 MB
__device__ int   g_off[4 * (NMAX + 1)];                 // CSR row offsets per etype
__device__ int   g_cur[4 * NMAX];                       // atomic cursors
__device__ int   g_adj[4 * EMAX];                       // CSR adjacency (src ids)
__device__ float g_agg[4 * (size_t)NMAX * DH];          // 204.8 MB
__device__ float g_h  [2 * (size_t)NMAX * DH];          // 102.4 MB

// ---------------- degree count ----------------
__global__ void deg_kernel(const int* __restrict__ idx, int* __restrict__ deg, int nE) {
    int i = blockIdx.x * blockDim.x + threadIdx.x;
    if (i < nE) atomicAdd(&deg[idx[i]], 1);
}

__global__ void rs_kernel(const int* __restrict__ deg, float* __restrict__ rs, int n) {
    int i = blockIdx.x * blockDim.x + threadIdx.x;
    if (i < n) rs[i] = rsqrtf(fmaxf((float)deg[i], 1.0f));
}

// ---------------- exclusive prefix scan of in-degrees -> CSR offsets + cursors ----
// one block (1024 threads) per etype; blockIdx.x = etype
__global__ __launch_bounds__(1024)
void scan_kernel(const int* __restrict__ deg, int* __restrict__ off,
                 int* __restrict__ cur, int N) {
    int e = blockIdx.x;
    const int* d = deg + (size_t)(2 * e + 1) * N;   // in-degree array of etype e
    int* o = off + (size_t)e * (N + 1);
    int* c = cur + (size_t)e * N;

    int tid  = threadIdx.x;
    int per  = (N + 1023) / 1024;
    int s0   = tid * per;
    int s1   = min(s0 + per, N);

    int sum = 0;
    for (int i = s0; i < s1; i++) sum += d[i];

    // block exclusive scan of per-thread sums
    __shared__ int wtot[32];
    int lane = tid & 31, wid = tid >> 5;
    int incl = sum;
#pragma unroll
    for (int ofs = 1; ofs < 32; ofs <<= 1) {
        int t = __shfl_up_sync(0xffffffffu, incl, ofs);
        if (lane >= ofs) incl += t;
    }
    if (lane == 31) wtot[wid] = incl;
    __syncthreads();
    if (wid == 0) {
        int w = wtot[lane];
        int wi = w;
#pragma unroll
        for (int ofs = 1; ofs < 32; ofs <<= 1) {
            int t = __shfl_up_sync(0xffffffffu, wi, ofs);
            if (lane >= ofs) wi += t;
        }
        wtot[lane] = wi - w;   // exclusive warp offsets
    }
    __syncthreads();
    int excl = wtot[wid] + incl - sum;

    int running = excl;
    for (int i = s0; i < s1; i++) {
        o[i] = running;
        c[i] = running;
        running += d[i];
    }
    if (s0 < N && s1 == N) o[N] = running;
}

// ---------------- CSR fill: adj[slot] = src ----------------
__global__ void fill_kernel(const int* __restrict__ src, const int* __restrict__ dst,
                            int* __restrict__ cur, int* __restrict__ adj, int nE) {
    int i = blockIdx.x * blockDim.x + threadIdx.x;
    if (i < nE) {
        int p = atomicAdd(&cur[dst[i]], 1);
        adj[p] = src[i];
    }
}

// ---------------- CSR aggregation: agg[d] = rs_in[d] * sum_{s in adj(d)} x[s]*rs_out[s]
// one warp per dst node; coalesced adjacency reads; single plain store per row
__global__ __launch_bounds__(256)
void aggcsr_kernel(const float* __restrict__ x, const float* __restrict__ rs_out,
                   const float* __restrict__ rs_in, const int* __restrict__ off,
                   const int* __restrict__ adj, float* __restrict__ agg, int nN) {
    int w    = (int)((blockIdx.x * blockDim.x + threadIdx.x) >> 5);
    int lane = threadIdx.x & 31;
    if (w >= nN) return;
    int s0 = __ldg(off + w);
    int s1 = __ldg(off + w + 1);

    float4 acc = make_float4(0.f, 0.f, 0.f, 0.f);
    for (int base = s0; base < s1; base += 32) {
        int n = min(32, s1 - base);
        int sid = 0; float rv = 0.f;
        if (lane < n) {
            sid = __ldg(adj + base + lane);
            rv  = __ldg(rs_out + sid);
        }
#pragma unroll 4
        for (int j = 0; j < n; j++) {
            int   s  = __shfl_sync(0xffffffffu, sid, j);
            float sc = __shfl_sync(0xffffffffu, rv,  j);
            float4 v = __ldg((const float4*)(x + (size_t)s * DH) + lane);
            acc.x += sc * v.x;
            acc.y += sc * v.y;
            acc.z += sc * v.z;
            acc.w += sc * v.w;
        }
    }
    float ri = __ldg(rs_in + w);
    acc.x *= ri; acc.y *= ri; acc.z *= ri; acc.w *= ri;
    ((float4*)(agg + (size_t)w * DH))[lane] = acc;
}

// ---------------- fused pair-GEMM with packed f32x2 FMAs ----------------
// out = maybe_relu(A0 @ W0 + b0) + maybe_relu(A1 @ W1 + b1)   (rs_in pre-folded into A)
extern __shared__ float s_mem[];

__global__ __launch_bounds__(256, 2)
void gemm_pair_kernel(const float* __restrict__ A0, const float* __restrict__ W0,
                      const float* __restrict__ b0,
                      const float* __restrict__ A1, const float* __restrict__ W1,
                      const float* __restrict__ b1,
                      float* __restrict__ out, int nrows, int act) {
    float* Ws = s_mem;               // 128*128 floats = 64 KB
    float* As = s_mem + DH * DH;     // 64*132 floats  = 33.8 KB

    int tid = threadIdx.x;
    int tx = tid & 15;               // col group (8 cols each)
    int ty = tid >> 4;               // row group (4 rows each)
    int row0 = blockIdx.x * BM;

    float accF[4][8];
#pragma unroll
    for (int r = 0; r < 4; r++)
#pragma unroll
        for (int c = 0; c < 8; c++) accF[r][c] = 0.f;

#pragma unroll 1
    for (int pass = 0; pass < 2; pass++) {
        const float* A  = pass ? A1 : A0;
        const float* W  = pass ? W1 : W0;
        const float* bb = pass ? b1 : b0;

        __syncthreads();
        // stage W (128x128)
        {
            const float4* Wv  = (const float4*)W;
            float4*       Wsv = (float4*)Ws;
#pragma unroll
            for (int i = 0; i < 16; i++) Wsv[tid + i * 256] = __ldg(Wv + tid + i * 256);
        }
        // stage A tile (64x128)
#pragma unroll
        for (int i = 0; i < 8; i++) {
            int idx = tid + i * 256;
            int r   = idx >> 5;
            int c4  = idx & 31;
            int grow = row0 + r;
            float4 v = make_float4(0.f, 0.f, 0.f, 0.f);
            if (grow < nrows) v = __ldg((const float4*)(A + (size_t)grow * DH) + c4);
            *((float4*)(As + r * APITCH) + c4) = v;
        }
        __syncthreads();

        u64t acc2[4][4];
#pragma unroll
        for (int r = 0; r < 4; r++)
#pragma unroll
            for (int c = 0; c < 4; c++) acc2[r][c] = 0ull;

#pragma unroll 2
        for (int k = 0; k < DH; k += 4) {
            float4 a[4];
#pragma unroll
            for (int r = 0; r < 4; r++)
                a[r] = *(const float4*)(As + (4 * ty + r) * APITCH + k);
#pragma unroll
            for (int kk = 0; kk < 4; kk++) {
                const u64t* wrow = (const u64t*)(Ws + (k + kk) * DH + tx * 8);
                u64t w2[4];
#pragma unroll
                for (int c = 0; c < 4; c++) w2[c] = wrow[c];
#pragma unroll
                for (int r = 0; r < 4; r++) {
                    float av = (kk == 0) ? a[r].x : (kk == 1) ? a[r].y
                             : (kk == 2) ? a[r].z : a[r].w;
                    u64t a2; PACK_DUP(a2, av);
                    FMA2(acc2[r][0], a2, w2[0], acc2[r][0]);
                    FMA2(acc2[r][1], a2, w2[1], acc2[r][1]);
                    FMA2(acc2[r][2], a2, w2[2], acc2[r][2]);
                    FMA2(acc2[r][3], a2, w2[3], acc2[r][3]);
                }
            }
        }

        float bl[8];
#pragma unroll
        for (int c = 0; c < 8; c++) bl[c] = __ldg(bb + tx * 8 + c);
#pragma unroll
        for (int r = 0; r < 4; r++)
#pragma unroll
            for (int c = 0; c < 4; c++) {
                float lo, hi;
                UNPACK2(lo, hi, acc2[r][c]);
                float v0 = lo + bl[2 * c];
                float v1 = hi + bl[2 * c + 1];
                if (act) { v0 = fmaxf(v0, 0.f); v1 = fmaxf(v1, 0.f); }
                accF[r][2 * c]     += v0;
                accF[r][2 * c + 1] += v1;
            }
    }

#pragma unroll
    for (int r = 0; r < 4; r++) {
        int grow = row0 + 4 * ty + r;
        if (grow < nrows) {
            float4 o0 = make_float4(accF[r][0], accF[r][1], accF[r][2], accF[r][3]);
            float4 o1 = make_float4(accF[r][4], accF[r][5], accF[r][6], accF[r][7]);
            *((float4*)(out + (size_t)grow * DH + tx * 8))     = o0;
            *((float4*)(out + (size_t)grow * DH + tx * 8 + 4)) = o1;
        }
    }
}

// ---------------- LayerNorm, in place, warp per row ----------------
__global__ __launch_bounds__(256)
void ln_kernel(float* __restrict__ data, const float* __restrict__ g0,
               const float* __restrict__ b0, int nA, int nTot) {
    int w    = (int)((blockIdx.x * blockDim.x + threadIdx.x) >> 5);
    int lane = threadIdx.x & 31;
    if (w >= nTot) return;
    int off = (w < nA) ? 0 : DH;
    float* row = data + (size_t)w * DH;
    float4 v = ((const float4*)row)[lane];
    float s  = v.x + v.y + v.z + v.w;
    float sq = v.x * v.x + v.y * v.y + v.z * v.z + v.w * v.w;
#pragma unroll
    for (int o = 16; o > 0; o >>= 1) {
        s  += __shfl_xor_sync(0xffffffffu, s, o);
        sq += __shfl_xor_sync(0xffffffffu, sq, o);
    }
    float mean = s * (1.f / 128.f);
    float var  = sq * (1.f / 128.f) - mean * mean;
    float inv  = rsqrtf(var + 1e-5f);
    float4 g = __ldg((const float4*)(g0 + off) + lane);
    float4 b = __ldg((const float4*)(b0 + off) + lane);
    float4 o;
    o.x = (v.x - mean) * inv * g.x + b.x;
    o.y = (v.y - mean) * inv * g.y + b.y;
    o.z = (v.z - mean) * inv * g.z + b.z;
    o.w = (v.w - mean) * inv * g.w + b.w;
    ((float4*)row)[lane] = o;
}

// ---------------- host orchestration ----------------
extern "C" void kernel_launch(void* const* d_in, const int* in_sizes, int n_in,
                              void* d_out, int out_size) {
    const float* x_A  = (const float*)d_in[0];
    const float* x_B  = (const float*)d_in[1];
    const float* W0   = (const float*)d_in[2];
    const float* b0   = (const float*)d_in[3];
    const float* W1   = (const float*)d_in[4];
    const float* b1   = (const float*)d_in[5];
    const float* ln_g = (const float*)d_in[6];
    const float* ln_b = (const float*)d_in[7];
    const int* eidx[8];
    int        esz[8];
    for (int i = 0; i < 8; i++) { eidx[i] = (const int*)d_in[8 + i]; esz[i] = in_sizes[8 + i]; }
    // eidx order: src_aa, dst_aa, src_ab, dst_ab, src_ba, dst_ba, src_bb, dst_bb

    const int N  = in_sizes[0] / DH;
    const int DD = DH * DH;
    float* out = (float*)d_out;

    int *deg, *off, *cur, *adj; float *rs, *agg, *h;
    cudaGetSymbolAddress((void**)&deg, g_deg);
    cudaGetSymbolAddress((void**)&rs,  g_rs);
    cudaGetSymbolAddress((void**)&off, g_off);
    cudaGetSymbolAddress((void**)&cur, g_cur);
    cudaGetSymbolAddress((void**)&adj, g_adj);
    cudaGetSymbolAddress((void**)&agg, g_agg);
    cudaGetSymbolAddress((void**)&h,   g_h);

    const size_t ND = (size_t)N * DH;
    float* aggp[4] = { agg, agg + ND, agg + 2 * ND, agg + 3 * ND };

    const int smem_bytes = (DH * DH + BM * APITCH) * 4;
    cudaFuncSetAttribute(gemm_pair_kernel, cudaFuncAttributeMaxDynamicSharedMemorySize, smem_bytes);

    // ---- degrees ----
    cudaMemsetAsync(deg, 0, 8 * (size_t)N * sizeof(int));
    for (int j = 0; j < 8; j++)
        deg_kernel<<<(esz[j] + 255) / 256, 256>>>(eidx[j], deg + (size_t)j * N, esz[j]);
    rs_kernel<<<(8 * N + 255) / 256, 256>>>(deg, rs, 8 * N);
    // rs layout: rs_out[e] = rs + 2e*N ; rs_in[e] = rs + (2e+1)*N

    // ---- CSR build (per etype, reused by both layers) ----
    scan_kernel<<<4, 1024>>>(deg, off, cur, N);
    for (int e = 0; e < 4; e++)
        fill_kernel<<<(esz[2 * e] + 255) / 256, 256>>>(
            eidx[2 * e], eidx[2 * e + 1],
            cur + (size_t)e * N, adj + (size_t)e * EMAX, esz[2 * e]);

    const int agg_blocks  = (N * 32 + 255) / 256;
    const int gemm_blocks = (N + BM - 1) / BM;

    // =================== layer 0 ===================
    {
        const float* xsrc[4] = { x_A, x_A, x_B, x_B };   // etype 0:aa 1:ab 2:ba 3:bb
        for (int e = 0; e < 4; e++)
            aggcsr_kernel<<<agg_blocks, 256>>>(
                xsrc[e], rs + (size_t)(2 * e) * N, rs + (size_t)(2 * e + 1) * N,
                off + (size_t)e * (N + 1), adj + (size_t)e * EMAX, aggp[e], N);
    }
    // dst A: etypes aa(0) + ba(2);  dst B: ab(1) + bb(3)
    gemm_pair_kernel<<<gemm_blocks, 256, smem_bytes>>>(
        aggp[0], W0 + 0 * DD, b0 + 0 * DH,
        aggp[2], W0 + 2 * DD, b0 + 2 * DH, h, N, /*act=*/1);
    gemm_pair_kernel<<<gemm_blocks, 256, smem_bytes>>>(
        aggp[1], W0 + 1 * DD, b0 + 1 * DH,
        aggp[3], W0 + 3 * DD, b0 + 3 * DH, h + ND, N, /*act=*/1);
    ln_kernel<<<(2 * N + 7) / 8, 256>>>(h, ln_g + 0, ln_b + 0, N, 2 * N);

    // =================== layer 1 ===================
    {
        const float* hsrc[4] = { h, h, h + ND, h + ND };
        for (int e = 0; e < 4; e++)
            aggcsr_kernel<<<agg_blocks, 256>>>(
                hsrc[e], rs + (size_t)(2 * e) * N, rs + (size_t)(2 * e + 1) * N,
                off + (size_t)e * (N + 1), adj + (size_t)e * EMAX, aggp[e], N);
    }
    gemm_pair_kernel<<<gemm_blocks, 256, smem_bytes>>>(
        aggp[0], W1 + 0 * DD, b1 + 0 * DH,
        aggp[2], W1 + 2 * DD, b1 + 2 * DH, out, N, /*act=*/0);
    gemm_pair_kernel<<<gemm_blocks, 256, smem_bytes>>>(
        aggp[1], W1 + 1 * DD, b1 + 1 * DH,
        aggp[3], W1 + 3 * DD, b1 + 3 * DH, out + ND, N, /*act=*/0);
    ln_kernel<<<(2 * N + 7) / 8, 256>>>(out, ln_g + 2 * DH, ln_b + 2 * DH, N, 2 * N);
}

// round 4
// speedup vs baseline: 1.5608x; 1.0259x over previous
#include <cuda_runtime.h>
#include <cstdint>

#define NMAX 100000
#define EMAX 1600000
#define DH   128
#define BM   128           // gemm tile rows
#define APITCH 132         // padded A-tile pitch (floats)

typedef unsigned long long u64t;

#define FMA2(d, a, b, c) \
    asm("fma.rn.f32x2 %0, %1, %2, %3;" : "=l"(d) : "l"(a), "l"(b), "l"(c))
#define PACK_DUP(d, f) \
    asm("mov.b64 %0, {%1, %1};" : "=l"(d) : "f"(f))
#define UNPACK2(lo, hi, v) \
    asm("mov.b64 {%0, %1}, %2;" : "=f"(lo), "=f"(hi) : "l"(v))

// ---------------- scratch (static device globals; no allocation) ----------------
__device__ int   g_deg[8 * NMAX];
__device__ float g_rs [8 * NMAX];
__device__ int   g_off[4 * (NMAX + 1)];
__device__ int   g_cur[4 * NMAX];
__device__ int   g_adj[4 * EMAX];
__device__ float g_agg[4 * (size_t)NMAX * DH];
__device__ float g_h  [2 * (size_t)NMAX * DH];

// ---------------- fused degree count over 8 index arrays ----------------
struct Ptr8 { const int* p[8]; int cum[9]; };

__global__ __launch_bounds__(256)
void deg8_kernel(Ptr8 P, int* __restrict__ deg, int N) {
    int i = blockIdx.x * blockDim.x + threadIdx.x;
    if (i >= P.cum[8]) return;
    int j = 0;
#pragma unroll
    for (int t = 1; t < 8; t++) j += (i >= P.cum[t]);
    int idx = __ldg(P.p[j] + (i - P.cum[j]));
    atomicAdd(&deg[j * N + idx], 1);
}

__global__ void rs_kernel(const int* __restrict__ deg, float* __restrict__ rs, int n) {
    int i = blockIdx.x * blockDim.x + threadIdx.x;
    if (i < n) rs[i] = rsqrtf(fmaxf((float)deg[i], 1.0f));
}

// ---------------- exclusive prefix scan of in-degrees -> CSR offsets + cursors ----
__global__ __launch_bounds__(1024)
void scan_kernel(const int* __restrict__ deg, int* __restrict__ off,
                 int* __restrict__ cur, int N) {
    int e = blockIdx.x;
    const int* d = deg + (size_t)(2 * e + 1) * N;
    int* o = off + (size_t)e * (N + 1);
    int* c = cur + (size_t)e * N;

    int tid  = threadIdx.x;
    int per  = (N + 1023) / 1024;
    int s0   = tid * per;
    int s1   = min(s0 + per, N);

    int sum = 0;
    for (int i = s0; i < s1; i++) sum += d[i];

    __shared__ int wtot[32];
    int lane = tid & 31, wid = tid >> 5;
    int incl = sum;
#pragma unroll
    for (int ofs = 1; ofs < 32; ofs <<= 1) {
        int t = __shfl_up_sync(0xffffffffu, incl, ofs);
        if (lane >= ofs) incl += t;
    }
    if (lane == 31) wtot[wid] = incl;
    __syncthreads();
    if (wid == 0) {
        int w = wtot[lane];
        int wi = w;
#pragma unroll
        for (int ofs = 1; ofs < 32; ofs <<= 1) {
            int t = __shfl_up_sync(0xffffffffu, wi, ofs);
            if (lane >= ofs) wi += t;
        }
        wtot[lane] = wi - w;
    }
    __syncthreads();
    int excl = wtot[wid] + incl - sum;

    int running = excl;
    for (int i = s0; i < s1; i++) {
        o[i] = running;
        c[i] = running;
        running += d[i];
    }
    if (s0 < N && s1 == N) o[N] = running;
}

// ---------------- fused CSR fill over 4 etypes ----------------
struct Fill4 { const int* src[4]; const int* dst[4]; int cum[5]; };

__global__ __launch_bounds__(256)
void fill4_kernel(Fill4 F, int* __restrict__ cur, int* __restrict__ adj, int N) {
    int i = blockIdx.x * blockDim.x + threadIdx.x;
    if (i >= F.cum[4]) return;
    int e = 0;
#pragma unroll
    for (int t = 1; t < 4; t++) e += (i >= F.cum[t]);
    int k = i - F.cum[e];
    int d = __ldg(F.dst[e] + k);
    int p = atomicAdd(&cur[e * N + d], 1);
    adj[(size_t)e * EMAX + p] = __ldg(F.src[e] + k);
}

// ---------------- CSR aggregation, all 4 etypes in one launch (blockIdx.y=etype) --
__global__ __launch_bounds__(256)
void aggcsr_kernel(const float* __restrict__ xA, const float* __restrict__ xB,
                   const float* __restrict__ rs, const int* __restrict__ offA,
                   const int* __restrict__ adjA, float* __restrict__ aggA, int nN) {
    int e    = blockIdx.y;
    int w    = (int)((blockIdx.x * blockDim.x + threadIdx.x) >> 5);
    int lane = threadIdx.x & 31;
    if (w >= nN) return;

    const float* x      = (e < 2) ? xA : xB;       // etype 0:aa 1:ab 2:ba 3:bb
    const float* rs_out = rs + (size_t)(2 * e) * nN;
    const float* rs_in  = rs + (size_t)(2 * e + 1) * nN;
    const int*   off    = offA + (size_t)e * (nN + 1);
    const int*   adj    = adjA + (size_t)e * EMAX;
    float*       agg    = aggA + (size_t)e * nN * DH;

    int s0 = __ldg(off + w);
    int s1 = __ldg(off + w + 1);

    float4 acc = make_float4(0.f, 0.f, 0.f, 0.f);
    for (int base = s0; base < s1; base += 32) {
        int n = min(32, s1 - base);
        int sid = 0; float rv = 0.f;
        if (lane < n) {
            sid = __ldg(adj + base + lane);
            rv  = __ldg(rs_out + sid);
        }
#pragma unroll 4
        for (int j = 0; j < n; j++) {
            int   s  = __shfl_sync(0xffffffffu, sid, j);
            float sc = __shfl_sync(0xffffffffu, rv,  j);
            float4 v = __ldg((const float4*)(x + (size_t)s * DH) + lane);
            acc.x += sc * v.x;
            acc.y += sc * v.y;
            acc.z += sc * v.z;
            acc.w += sc * v.w;
        }
    }
    float ri = __ldg(rs_in + w);
    acc.x *= ri; acc.y *= ri; acc.z *= ri; acc.w *= ri;
    ((float4*)(agg + (size_t)w * DH))[lane] = acc;
}

// ---------------- fused pair-GEMM + LayerNorm epilogue ----------------
// out = LN( maybe_relu(A0@W0+b0) + maybe_relu(A1@W1+b1) ; gamma,beta )
// 256 threads; tile 128 rows x 128 cols; 8x8 per thread; f32x2 FMAs.
// thread grid: ty=tid>>4 (16 row groups of 8), tx=tid&15 (16 col groups of 8)
extern __shared__ float s_mem[];

__global__ __launch_bounds__(256, 1)
void gemm_pair_ln_kernel(const float* __restrict__ A0, const float* __restrict__ W0,
                         const float* __restrict__ b0,
                         const float* __restrict__ A1, const float* __restrict__ W1,
                         const float* __restrict__ b1,
                         const float* __restrict__ gamma, const float* __restrict__ beta,
                         float* __restrict__ out, int nrows, int act) {
    float* Ws = s_mem;                 // 128*128 floats = 64 KB
    float* As = s_mem + DH * DH;       // 128*132 floats = 66 KB

    int tid = threadIdx.x;
    int tx = tid & 15;
    int ty = tid >> 4;
    int row0 = blockIdx.x * BM;

    float accF[8][8];
#pragma unroll
    for (int r = 0; r < 8; r++)
#pragma unroll
        for (int c = 0; c < 8; c++) accF[r][c] = 0.f;

#pragma unroll 1
    for (int pass = 0; pass < 2; pass++) {
        const float* A  = pass ? A1 : A0;
        const float* W  = pass ? W1 : W0;
        const float* bb = pass ? b1 : b0;

        __syncthreads();
        // stage W (128x128) : 4096 float4 / 256 threads = 16 each
        {
            const float4* Wv  = (const float4*)W;
            float4*       Wsv = (float4*)Ws;
#pragma unroll
            for (int i = 0; i < 16; i++) Wsv[tid + i * 256] = __ldg(Wv + tid + i * 256);
        }
        // stage A tile (128x128): 4096 float4 slots
#pragma unroll
        for (int i = 0; i < 16; i++) {
            int idx = tid + i * 256;
            int r   = idx >> 5;
            int c4  = idx & 31;
            int grow = row0 + r;
            float4 v = make_float4(0.f, 0.f, 0.f, 0.f);
            if (grow < nrows) v = __ldg((const float4*)(A + (size_t)grow * DH) + c4);
            *((float4*)(As + r * APITCH) + c4) = v;
        }
        __syncthreads();

        u64t acc2[8][4];
#pragma unroll
        for (int r = 0; r < 8; r++)
#pragma unroll
            for (int c = 0; c < 4; c++) acc2[r][c] = 0ull;

#pragma unroll 1
        for (int k = 0; k < DH; k += 4) {
            float4 a[8];
#pragma unroll
            for (int r = 0; r < 8; r++)
                a[r] = *(const float4*)(As + (ty * 8 + r) * APITCH + k);
#pragma unroll
            for (int kk = 0; kk < 4; kk++) {
                const u64t* wrow = (const u64t*)(Ws + (k + kk) * DH + tx * 8);
                u64t w2[4];
#pragma unroll
                for (int c = 0; c < 4; c++) w2[c] = wrow[c];
#pragma unroll
                for (int r = 0; r < 8; r++) {
                    float av = (kk == 0) ? a[r].x : (kk == 1) ? a[r].y
                             : (kk == 2) ? a[r].z : a[r].w;
                    u64t a2; PACK_DUP(a2, av);
                    FMA2(acc2[r][0], a2, w2[0], acc2[r][0]);
                    FMA2(acc2[r][1], a2, w2[1], acc2[r][1]);
                    FMA2(acc2[r][2], a2, w2[2], acc2[r][2]);
                    FMA2(acc2[r][3], a2, w2[3], acc2[r][3]);
                }
            }
        }

        float bl[8];
#pragma unroll
        for (int c = 0; c < 8; c++) bl[c] = __ldg(bb + tx * 8 + c);
#pragma unroll
        for (int r = 0; r < 8; r++)
#pragma unroll
            for (int c = 0; c < 4; c++) {
                float lo, hi;
                UNPACK2(lo, hi, acc2[r][c]);
                float v0 = lo + bl[2 * c];
                float v1 = hi + bl[2 * c + 1];
                if (act) { v0 = fmaxf(v0, 0.f); v1 = fmaxf(v1, 0.f); }
                accF[r][2 * c]     += v0;
                accF[r][2 * c + 1] += v1;
            }
    }

    // ---- fused LayerNorm over each row (16 lanes x 8 cols = 128) ----
    float gl[8], be[8];
#pragma unroll
    for (int c = 0; c < 8; c++) {
        gl[c] = __ldg(gamma + tx * 8 + c);
        be[c] = __ldg(beta  + tx * 8 + c);
    }
#pragma unroll
    for (int r = 0; r < 8; r++) {
        float s = 0.f, sq = 0.f;
#pragma unroll
        for (int c = 0; c < 8; c++) {
            s  += accF[r][c];
            sq += accF[r][c] * accF[r][c];
        }
#pragma unroll
        for (int o = 8; o > 0; o >>= 1) {
            s  += __shfl_xor_sync(0xffffffffu, s,  o);
            sq += __shfl_xor_sync(0xffffffffu, sq, o);
        }
        float mean = s * (1.f / 128.f);
        float var  = sq * (1.f / 128.f) - mean * mean;
        float inv  = rsqrtf(var + 1e-5f);

        int grow = row0 + ty * 8 + r;
        if (grow < nrows) {
            float4 o0, o1;
            o0.x = (accF[r][0] - mean) * inv * gl[0] + be[0];
            o0.y = (accF[r][1] - mean) * inv * gl[1] + be[1];
            o0.z = (accF[r][2] - mean) * inv * gl[2] + be[2];
            o0.w = (accF[r][3] - mean) * inv * gl[3] + be[3];
            o1.x = (accF[r][4] - mean) * inv * gl[4] + be[4];
            o1.y = (accF[r][5] - mean) * inv * gl[5] + be[5];
            o1.z = (accF[r][6] - mean) * inv * gl[6] + be[6];
            o1.w = (accF[r][7] - mean) * inv * gl[7] + be[7];
            *((float4*)(out + (size_t)grow * DH + tx * 8))     = o0;
            *((float4*)(out + (size_t)grow * DH + tx * 8 + 4)) = o1;
        }
    }
}

// ---------------- host orchestration ----------------
extern "C" void kernel_launch(void* const* d_in, const int* in_sizes, int n_in,
                              void* d_out, int out_size) {
    const float* x_A  = (const float*)d_in[0];
    const float* x_B  = (const float*)d_in[1];
    const float* W0   = (const float*)d_in[2];
    const float* b0   = (const float*)d_in[3];
    const float* W1   = (const float*)d_in[4];
    const float* b1   = (const float*)d_in[5];
    const float* ln_g = (const float*)d_in[6];
    const float* ln_b = (const float*)d_in[7];
    const int* eidx[8];
    int        esz[8];
    for (int i = 0; i < 8; i++) { eidx[i] = (const int*)d_in[8 + i]; esz[i] = in_sizes[8 + i]; }
    // order: src_aa, dst_aa, src_ab, dst_ab, src_ba, dst_ba, src_bb, dst_bb

    const int N  = in_sizes[0] / DH;
    const int DD = DH * DH;
    float* out = (float*)d_out;

    int *deg, *off, *cur, *adj; float *rs, *agg, *h;
    cudaGetSymbolAddress((void**)&deg, g_deg);
    cudaGetSymbolAddress((void**)&rs,  g_rs);
    cudaGetSymbolAddress((void**)&off, g_off);
    cudaGetSymbolAddress((void**)&cur, g_cur);
    cudaGetSymbolAddress((void**)&adj, g_adj);
    cudaGetSymbolAddress((void**)&agg, g_agg);
    cudaGetSymbolAddress((void**)&h,   g_h);

    const size_t ND = (size_t)N * DH;

    const int smem_bytes = (DH * DH + BM * APITCH) * 4;
    cudaFuncSetAttribute(gemm_pair_ln_kernel, cudaFuncAttributeMaxDynamicSharedMemorySize, smem_bytes);

    // ---- degrees: one fused launch over all 8 index arrays ----
    cudaMemsetAsync(deg, 0, 8 * (size_t)N * sizeof(int));
    Ptr8 P; P.cum[0] = 0;
    for (int j = 0; j < 8; j++) { P.p[j] = eidx[j]; P.cum[j + 1] = P.cum[j] + esz[j]; }
    deg8_kernel<<<(P.cum[8] + 255) / 256, 256>>>(P, deg, N);
    rs_kernel<<<(8 * N + 255) / 256, 256>>>(deg, rs, 8 * N);

    // ---- CSR build ----
    scan_kernel<<<4, 1024>>>(deg, off, cur, N);
    Fill4 F; F.cum[0] = 0;
    for (int e = 0; e < 4; e++) {
        F.src[e] = eidx[2 * e]; F.dst[e] = eidx[2 * e + 1];
        F.cum[e + 1] = F.cum[e] + esz[2 * e];
    }
    fill4_kernel<<<(F.cum[4] + 255) / 256, 256>>>(F, cur, adj, N);

    dim3 agg_grid((N * 32 + 255) / 256, 4);
    const int gemm_blocks = (N + BM - 1) / BM;

    // =================== layer 0 ===================
    aggcsr_kernel<<<agg_grid, 256>>>(x_A, x_B, rs, off, adj, agg, N);
    // dst A: etypes aa(0)+ba(2); dst B: ab(1)+bb(3)
    gemm_pair_ln_kernel<<<gemm_blocks, 256, smem_bytes>>>(
        agg + 0 * ND, W0 + 0 * DD, b0 + 0 * DH,
        agg + 2 * ND, W0 + 2 * DD, b0 + 2 * DH,
        ln_g + 0 * DH, ln_b + 0 * DH, h, N, /*act=*/1);
    gemm_pair_ln_kernel<<<gemm_blocks, 256, smem_bytes>>>(
        agg + 1 * ND, W0 + 1 * DD, b0 + 1 * DH,
        agg + 3 * ND, W0 + 3 * DD, b0 + 3 * DH,
        ln_g + 1 * DH, ln_b + 1 * DH, h + ND, N, /*act=*/1);

    // =================== layer 1 ===================
    aggcsr_kernel<<<agg_grid, 256>>>(h, h + ND, rs, off, adj, agg, N);
    gemm_pair_ln_kernel<<<gemm_blocks, 256, smem_bytes>>>(
        agg + 0 * ND, W1 + 0 * DD, b1 + 0 * DH,
        agg + 2 * ND, W1 + 2 * DD, b1 + 2 * DH,
        ln_g + 2 * DH, ln_b + 2 * DH, out, N, /*act=*/0);
    gemm_pair_ln_kernel<<<gemm_blocks, 256, smem_bytes>>>(
        agg + 1 * ND, W1 + 1 * DD, b1 + 1 * DH,
        agg + 3 * ND, W1 + 3 * DD, b1 + 3 * DH,
        ln_g + 3 * DH, ln_b + 3 * DH, out + ND, N, /*act=*/0);
}

// round 5
// speedup vs baseline: 1.6553x; 1.0605x over previous
#include <cuda_runtime.h>
#include <cuda_fp16.h>
#include <cstdint>

#define NMAX 100000
#define EMAX 1600000
#define DH   128
#define BM   128           // gemm tile rows
#define APITCH 132         // padded A-tile pitch (floats)

typedef unsigned long long u64t;

#define FMA2(d, a, b, c) \
    asm("fma.rn.f32x2 %0, %1, %2, %3;" : "=l"(d) : "l"(a), "l"(b), "l"(c))
#define PACK_DUP(d, f) \
    asm("mov.b64 %0, {%1, %1};" : "=l"(d) : "f"(f))
#define UNPACK2(lo, hi, v) \
    asm("mov.b64 {%0, %1}, %2;" : "=f"(lo), "=f"(hi) : "l"(v))

// ---------------- scratch (static device globals; no allocation) ----------------
__device__ int    g_deg[8 * NMAX];
__device__ float  g_rs [8 * NMAX];
__device__ int    g_off[4 * (NMAX + 1)];
__device__ int    g_cur[4 * NMAX];
__device__ int    g_adj[4 * EMAX];
__device__ float  g_agg[4 * (size_t)NMAX * DH];     // fp32 aggregated features
__device__ __half g_xh [2 * (size_t)NMAX * DH];     // fp16 staged layer-0 inputs
__device__ __half g_hh [2 * (size_t)NMAX * DH];     // fp16 hidden (layer-0 output)

// ---------------- fused degree count over 8 index arrays ----------------
struct Ptr8 { const int* p[8]; int cum[9]; };

__global__ __launch_bounds__(256)
void deg8_kernel(Ptr8 P, int* __restrict__ deg, int N) {
    int i = blockIdx.x * blockDim.x + threadIdx.x;
    if (i >= P.cum[8]) return;
    int j = 0;
#pragma unroll
    for (int t = 1; t < 8; t++) j += (i >= P.cum[t]);
    int idx = __ldg(P.p[j] + (i - P.cum[j]));
    atomicAdd(&deg[j * N + idx], 1);
}

__global__ void rs_kernel(const int* __restrict__ deg, float* __restrict__ rs, int n) {
    int i = blockIdx.x * blockDim.x + threadIdx.x;
    if (i < n) rs[i] = rsqrtf(fmaxf((float)deg[i], 1.0f));
}

// ---------------- exclusive prefix scan of in-degrees -> CSR offsets + cursors ----
__global__ __launch_bounds__(1024)
void scan_kernel(const int* __restrict__ deg, int* __restrict__ off,
                 int* __restrict__ cur, int N) {
    int e = blockIdx.x;
    const int* d = deg + (size_t)(2 * e + 1) * N;
    int* o = off + (size_t)e * (N + 1);
    int* c = cur + (size_t)e * N;

    int tid  = threadIdx.x;
    int per  = (N + 1023) / 1024;
    int s0   = tid * per;
    int s1   = min(s0 + per, N);

    int sum = 0;
    for (int i = s0; i < s1; i++) sum += d[i];

    __shared__ int wtot[32];
    int lane = tid & 31, wid = tid >> 5;
    int incl = sum;
#pragma unroll
    for (int ofs = 1; ofs < 32; ofs <<= 1) {
        int t = __shfl_up_sync(0xffffffffu, incl, ofs);
        if (lane >= ofs) incl += t;
    }
    if (lane == 31) wtot[wid] = incl;
    __syncthreads();
    if (wid == 0) {
        int w = wtot[lane];
        int wi = w;
#pragma unroll
        for (int ofs = 1; ofs < 32; ofs <<= 1) {
            int t = __shfl_up_sync(0xffffffffu, wi, ofs);
            if (lane >= ofs) wi += t;
        }
        wtot[lane] = wi - w;
    }
    __syncthreads();
    int excl = wtot[wid] + incl - sum;

    int running = excl;
    for (int i = s0; i < s1; i++) {
        o[i] = running;
        c[i] = running;
        running += d[i];
    }
    if (s0 < N && s1 == N) o[N] = running;
}

// ---------------- fused CSR fill over 4 etypes + fp32->fp16 convert of x ----------
struct Fill4 { const int* src[4]; const int* dst[4]; int cum[5]; };

__global__ __launch_bounds__(256)
void fill4cvt_kernel(Fill4 F, int* __restrict__ cur, int* __restrict__ adj, int N,
                     const float* __restrict__ xA, const float* __restrict__ xB,
                     __half* __restrict__ xh, int nCvt) {
    int i = blockIdx.x * blockDim.x + threadIdx.x;
    if (i < F.cum[4]) {
        int e = 0;
#pragma unroll
        for (int t = 1; t < 4; t++) e += (i >= F.cum[t]);
        int k = i - F.cum[e];
        int d = __ldg(F.dst[e] + k);
        int p = atomicAdd(&cur[e * N + d], 1);
        adj[(size_t)e * EMAX + p] = __ldg(F.src[e] + k);
    } else {
        int j = i - F.cum[4];
        if (j < nCvt) {                       // nCvt float4 chunks over [xA ; xB]
            int half_n = nCvt >> 1;
            float4 v = (j < half_n) ? __ldg((const float4*)xA + j)
                                    : __ldg((const float4*)xB + (j - half_n));
            __half2 h0 = __floats2half2_rn(v.x, v.y);
            __half2 h1 = __floats2half2_rn(v.z, v.w);
            ((__half2*)xh)[2 * j]     = h0;
            ((__half2*)xh)[2 * j + 1] = h1;
        }
    }
}

// ---------------- CSR aggregation (fp16 gather, fp32 accum), 4 etypes per launch --
__global__ __launch_bounds__(256)
void aggcsr_kernel(const __half* __restrict__ xh,      // [2N, DH] : [A rows; B rows]
                   const float* __restrict__ rs, const int* __restrict__ offA,
                   const int* __restrict__ adjA, float* __restrict__ aggA, int nN) {
    int e    = blockIdx.y;
    int w    = (int)((blockIdx.x * blockDim.x + threadIdx.x) >> 5);
    int lane = threadIdx.x & 31;
    if (w >= nN) return;

    const __half* x     = xh + ((e < 2) ? 0 : (size_t)nN * DH);  // 0:aa 1:ab 2:ba 3:bb
    const float* rs_out = rs + (size_t)(2 * e) * nN;
    const float* rs_in  = rs + (size_t)(2 * e + 1) * nN;
    const int*   off    = offA + (size_t)e * (nN + 1);
    const int*   adj    = adjA + (size_t)e * EMAX;
    float*       agg    = aggA + (size_t)e * nN * DH;

    int s0 = __ldg(off + w);
    int s1 = __ldg(off + w + 1);

    float4 acc = make_float4(0.f, 0.f, 0.f, 0.f);
    for (int base = s0; base < s1; base += 32) {
        int n = min(32, s1 - base);
        int sid = 0; float rv = 0.f;
        if (lane < n) {
            sid = __ldg(adj + base + lane);
            rv  = __ldg(rs_out + sid);
        }
#pragma unroll 4
        for (int j = 0; j < n; j++) {
            int   s  = __shfl_sync(0xffffffffu, sid, j);
            float sc = __shfl_sync(0xffffffffu, rv,  j);
            // lane covers 4 halfs = 8 bytes; warp covers the full 256B row
            uint2 raw = __ldg((const uint2*)(x + (size_t)s * DH) + lane);
            __half2 h0 = *(__half2*)&raw.x;
            __half2 h1 = *(__half2*)&raw.y;
            float2 f0 = __half22float2(h0);
            float2 f1 = __half22float2(h1);
            acc.x += sc * f0.x;
            acc.y += sc * f0.y;
            acc.z += sc * f1.x;
            acc.w += sc * f1.y;
        }
    }
    float ri = __ldg(rs_in + w);
    acc.x *= ri; acc.y *= ri; acc.z *= ri; acc.w *= ri;
    ((float4*)(agg + (size_t)w * DH))[lane] = acc;
}

// ---------------- fused pair-GEMM + LayerNorm; both dst ntypes in one launch ------
// blockIdx.y = g (dst ntype). passes use etypes g and g+2.
// out = LN( maybe_relu(agg_g @ W_g + b_g) + maybe_relu(agg_{g+2} @ W_{g+2} + b_{g+2}) )
// outh != nullptr -> write fp16 (layer 0), else write fp32 to outf (layer 1).
extern __shared__ float s_mem[];

__global__ __launch_bounds__(256, 1)
void gemm_pair_ln_kernel(const float* __restrict__ agg, const float* __restrict__ Wl,
                         const float* __restrict__ bl,
                         const float* __restrict__ gamma_l, const float* __restrict__ beta_l,
                         float* __restrict__ outf, __half* __restrict__ outh,
                         int nrows, int act) {
    float* Ws = s_mem;                 // 128*128 floats = 64 KB
    float* As = s_mem + DH * DH;       // 128*132 floats = 66 KB

    int tid = threadIdx.x;
    int tx = tid & 15;
    int ty = tid >> 4;
    int row0 = blockIdx.x * BM;
    int g    = blockIdx.y;
    const size_t ND = (size_t)nrows * DH;

    float accF[8][8];
#pragma unroll
    for (int r = 0; r < 8; r++)
#pragma unroll
        for (int c = 0; c < 8; c++) accF[r][c] = 0.f;

#pragma unroll 1
    for (int pass = 0; pass < 2; pass++) {
        int e = g + 2 * pass;                       // etypes: dstA {0,2}, dstB {1,3}
        const float* A  = agg + (size_t)e * ND;
        const float* W  = Wl + (size_t)e * DH * DH;
        const float* bb = bl + (size_t)e * DH;

        __syncthreads();
        {
            const float4* Wv  = (const float4*)W;
            float4*       Wsv = (float4*)Ws;
#pragma unroll
            for (int i = 0; i < 16; i++) Wsv[tid + i * 256] = __ldg(Wv + tid + i * 256);
        }
#pragma unroll
        for (int i = 0; i < 16; i++) {
            int idx = tid + i * 256;
            int r   = idx >> 5;
            int c4  = idx & 31;
            int grow = row0 + r;
            float4 v = make_float4(0.f, 0.f, 0.f, 0.f);
            if (grow < nrows) v = __ldg((const float4*)(A + (size_t)grow * DH) + c4);
            *((float4*)(As + r * APITCH) + c4) = v;
        }
        __syncthreads();

        u64t acc2[8][4];
#pragma unroll
        for (int r = 0; r < 8; r++)
#pragma unroll
            for (int c = 0; c < 4; c++) acc2[r][c] = 0ull;

#pragma unroll 1
        for (int k = 0; k < DH; k += 4) {
            float4 a[8];
#pragma unroll
            for (int r = 0; r < 8; r++)
                a[r] = *(const float4*)(As + (ty * 8 + r) * APITCH + k);
#pragma unroll
            for (int kk = 0; kk < 4; kk++) {
                const ulonglong2* wrow = (const ulonglong2*)(Ws + (k + kk) * DH + tx * 8);
                ulonglong2 wv0 = wrow[0];
                ulonglong2 wv1 = wrow[1];
#pragma unroll
                for (int r = 0; r < 8; r++) {
                    float av = (kk == 0) ? a[r].x : (kk == 1) ? a[r].y
                             : (kk == 2) ? a[r].z : a[r].w;
                    u64t a2; PACK_DUP(a2, av);
                    FMA2(acc2[r][0], a2, wv0.x, acc2[r][0]);
                    FMA2(acc2[r][1], a2, wv0.y, acc2[r][1]);
                    FMA2(acc2[r][2], a2, wv1.x, acc2[r][2]);
                    FMA2(acc2[r][3], a2, wv1.y, acc2[r][3]);
                }
            }
        }

        float blv[8];
#pragma unroll
        for (int c = 0; c < 8; c++) blv[c] = __ldg(bb + tx * 8 + c);
#pragma unroll
        for (int r = 0; r < 8; r++)
#pragma unroll
            for (int c = 0; c < 4; c++) {
                float lo, hi;
                UNPACK2(lo, hi, acc2[r][c]);
                float v0 = lo + blv[2 * c];
                float v1 = hi + blv[2 * c + 1];
                if (act) { v0 = fmaxf(v0, 0.f); v1 = fmaxf(v1, 0.f); }
                accF[r][2 * c]     += v0;
                accF[r][2 * c + 1] += v1;
            }
    }

    // ---- fused LayerNorm over each row (16 lanes x 8 cols = 128) ----
    const float* gamma = gamma_l + (size_t)g * DH;
    const float* beta  = beta_l  + (size_t)g * DH;
    float gl[8], be[8];
#pragma unroll
    for (int c = 0; c < 8; c++) {
        gl[c] = __ldg(gamma + tx * 8 + c);
        be[c] = __ldg(beta  + tx * 8 + c);
    }
#pragma unroll
    for (int r = 0; r < 8; r++) {
        float s = 0.f, sq = 0.f;
#pragma unroll
        for (int c = 0; c < 8; c++) {
            s  += accF[r][c];
            sq += accF[r][c] * accF[r][c];
        }
#pragma unroll
        for (int o = 8; o > 0; o >>= 1) {
            s  += __shfl_xor_sync(0xffffffffu, s,  o);
            sq += __shfl_xor_sync(0xffffffffu, sq, o);
        }
        float mean = s * (1.f / 128.f);
        float var  = sq * (1.f / 128.f) - mean * mean;
        float inv  = rsqrtf(var + 1e-5f);

        int grow = row0 + ty * 8 + r;
        if (grow < nrows) {
            float o0[8];
#pragma unroll
            for (int c = 0; c < 8; c++)
                o0[c] = (accF[r][c] - mean) * inv * gl[c] + be[c];
            size_t rowbase = (size_t)g * ND + (size_t)grow * DH + tx * 8;
            if (outh) {
                __half2 q0 = __floats2half2_rn(o0[0], o0[1]);
                __half2 q1 = __floats2half2_rn(o0[2], o0[3]);
                __half2 q2 = __floats2half2_rn(o0[4], o0[5]);
                __half2 q3 = __floats2half2_rn(o0[6], o0[7]);
                uint4 pk;
                pk.x = *(unsigned*)&q0; pk.y = *(unsigned*)&q1;
                pk.z = *(unsigned*)&q2; pk.w = *(unsigned*)&q3;
                *((uint4*)(outh + rowbase)) = pk;
            } else {
                float4 f0 = make_float4(o0[0], o0[1], o0[2], o0[3]);
                float4 f1 = make_float4(o0[4], o0[5], o0[6], o0[7]);
                *((float4*)(outf + rowbase))     = f0;
                *((float4*)(outf + rowbase + 4)) = f1;
            }
        }
    }
}

// ---------------- host orchestration ----------------
extern "C" void kernel_launch(void* const* d_in, const int* in_sizes, int n_in,
                              void* d_out, int out_size) {
    const float* x_A  = (const float*)d_in[0];
    const float* x_B  = (const float*)d_in[1];
    const float* W0   = (const float*)d_in[2];
    const float* b0   = (const float*)d_in[3];
    const float* W1   = (const float*)d_in[4];
    const float* b1   = (const float*)d_in[5];
    const float* ln_g = (const float*)d_in[6];
    const float* ln_b = (const float*)d_in[7];
    const int* eidx[8];
    int        esz[8];
    for (int i = 0; i < 8; i++) { eidx[i] = (const int*)d_in[8 + i]; esz[i] = in_sizes[8 + i]; }
    // order: src_aa, dst_aa, src_ab, dst_ab, src_ba, dst_ba, src_bb, dst_bb

    const int N = in_sizes[0] / DH;
    float* out = (float*)d_out;

    int *deg, *off, *cur, *adj; float *rs, *agg; __half *xh, *hh;
    cudaGetSymbolAddress((void**)&deg, g_deg);
    cudaGetSymbolAddress((void**)&rs,  g_rs);
    cudaGetSymbolAddress((void**)&off, g_off);
    cudaGetSymbolAddress((void**)&cur, g_cur);
    cudaGetSymbolAddress((void**)&adj, g_adj);
    cudaGetSymbolAddress((void**)&agg, g_agg);
    cudaGetSymbolAddress((void**)&xh,  g_xh);
    cudaGetSymbolAddress((void**)&hh,  g_hh);

    const int smem_bytes = (DH * DH + BM * APITCH) * 4;
    cudaFuncSetAttribute(gemm_pair_ln_kernel, cudaFuncAttributeMaxDynamicSharedMemorySize, smem_bytes);

    // 1) zero degree tables
    cudaMemsetAsync(deg, 0, 8 * (size_t)N * sizeof(int));
    // 2) fused degree count
    Ptr8 P; P.cum[0] = 0;
    for (int j = 0; j < 8; j++) { P.p[j] = eidx[j]; P.cum[j + 1] = P.cum[j] + esz[j]; }
    deg8_kernel<<<(P.cum[8] + 255) / 256, 256>>>(P, deg, N);
    // 3) rsqrt degrees
    rs_kernel<<<(8 * N + 255) / 256, 256>>>(deg, rs, 8 * N);
    // 4) CSR offsets
    scan_kernel<<<4, 1024>>>(deg, off, cur, N);
    // 5) CSR fill + x -> fp16 staging (fused)
    Fill4 F; F.cum[0] = 0;
    for (int e = 0; e < 4; e++) {
        F.src[e] = eidx[2 * e]; F.dst[e] = eidx[2 * e + 1];
        F.cum[e + 1] = F.cum[e] + esz[2 * e];
    }
    int nCvt = 2 * N * DH / 4;
    fill4cvt_kernel<<<(F.cum[4] + nCvt + 255) / 256, 256>>>(F, cur, adj, N,
                                                            x_A, x_B, xh, nCvt);

    dim3 agg_grid((N * 32 + 255) / 256, 4);
    dim3 gemm_grid((N + BM - 1) / BM, 2);

    // =================== layer 0 ===================
    aggcsr_kernel<<<agg_grid, 256>>>(xh, rs, off, adj, agg, N);      // 6th launch (profiled)
    gemm_pair_ln_kernel<<<gemm_grid, 256, smem_bytes>>>(
        agg, W0, b0, ln_g + 0 * DH, ln_b + 0 * DH,
        nullptr, hh, N, /*act=*/1);

    // =================== layer 1 ===================
    aggcsr_kernel<<<agg_grid, 256>>>(hh, rs, off, adj, agg, N);
    gemm_pair_ln_kernel<<<gemm_grid, 256, smem_bytes>>>(
        agg, W1, b1, ln_g + 2 * DH, ln_b + 2 * DH,
        out, nullptr, N, /*act=*/0);
}

// round 6
// speedup vs baseline: 1.7888x; 1.0807x over previous
#include <cuda_runtime.h>
#include <cuda_fp16.h>
#include <cstdint>

#define NMAX 100000
#define EMAX 1600000
#define DH   128
#define BM   128           // gemm tile rows
#define APITCH 132         // padded A-tile pitch (floats)

typedef unsigned long long u64t;

#define FMA2(d, a, b, c) \
    asm("fma.rn.f32x2 %0, %1, %2, %3;" : "=l"(d) : "l"(a), "l"(b), "l"(c))
#define PACK_DUP(d, f) \
    asm("mov.b64 %0, {%1, %1};" : "=l"(d) : "f"(f))
#define UNPACK2(lo, hi, v) \
    asm("mov.b64 {%0, %1}, %2;" : "=f"(lo), "=f"(hi) : "l"(v))

// ---------------- scratch (static device globals; no allocation) ----------------
__device__ int    g_deg [8 * NMAX];
__device__ float  g_rs  [8 * NMAX];
__device__ int    g_off [4 * (NMAX + 1)];
__device__ int    g_slot[4 * EMAX];                  // per-edge slot within dst row
__device__ int    g_adj [4 * EMAX];
__device__ __half g_aggh[4 * (size_t)NMAX * DH];     // fp16 aggregated features
__device__ __half g_xh  [2 * (size_t)NMAX * DH];     // fp16 staged layer-0 inputs
__device__ __half g_hh  [2 * (size_t)NMAX * DH];     // fp16 hidden (layer-0 out)

// ---------------- fused degree count; dst arrays also record edge slots ----------
struct Ptr8 { const int* p[8]; int cum[9]; };

__global__ __launch_bounds__(256)
void deg8_kernel(Ptr8 P, int* __restrict__ deg, int* __restrict__ slot, int N) {
    int i = blockIdx.x * blockDim.x + threadIdx.x;
    if (i >= P.cum[8]) return;
    int j = 0;
#pragma unroll
    for (int t = 1; t < 8; t++) j += (i >= P.cum[t]);
    int k = i - P.cum[j];
    int idx = __ldg(P.p[j] + k);
    int old = atomicAdd(&deg[j * N + idx], 1);
    if (j & 1) slot[(size_t)((j - 1) >> 1) * EMAX + k] = old;   // dst arrays: j=1,3,5,7
}

// ---------------- scan (4 blocks) + rsqrt degrees (4 blocks) ----------------
__global__ __launch_bounds__(1024)
void scan_rs_kernel(const int* __restrict__ deg, int* __restrict__ off,
                    float* __restrict__ rs, int N) {
    int b = blockIdx.x;
    if (b >= 4) {                      // rs: blocks 4..7 cover 8N elements
        int bb = b - 4;
        for (int i = bb * 2 * N + threadIdx.x; i < (bb + 1) * 2 * N; i += 1024)
            rs[i] = rsqrtf(fmaxf((float)__ldg(deg + i), 1.0f));
        return;
    }
    int e = b;
    const int* d = deg + (size_t)(2 * e + 1) * N;   // in-degree of etype e
    int* o = off + (size_t)e * (N + 1);

    int tid  = threadIdx.x;
    int per  = (N + 1023) / 1024;
    int s0   = tid * per;
    int s1   = min(s0 + per, N);

    int sum = 0;
    for (int i = s0; i < s1; i++) sum += d[i];

    __shared__ int wtot[32];
    int lane = tid & 31, wid = tid >> 5;
    int incl = sum;
#pragma unroll
    for (int ofs = 1; ofs < 32; ofs <<= 1) {
        int t = __shfl_up_sync(0xffffffffu, incl, ofs);
        if (lane >= ofs) incl += t;
    }
    if (lane == 31) wtot[wid] = incl;
    __syncthreads();
    if (wid == 0) {
        int w = wtot[lane];
        int wi = w;
#pragma unroll
        for (int ofs = 1; ofs < 32; ofs <<= 1) {
            int t = __shfl_up_sync(0xffffffffu, wi, ofs);
            if (lane >= ofs) wi += t;
        }
        wtot[lane] = wi - w;
    }
    __syncthreads();
    int excl = wtot[wid] + incl - sum;

    int running = excl;
    for (int i = s0; i < s1; i++) {
        o[i] = running;
        running += d[i];
    }
    if (s0 < N && s1 == N) o[N] = running;
}

// ---------------- atomic-free CSR fill + fp32->fp16 convert of x ----------------
struct Fill4 { const int* src[4]; const int* dst[4]; int cum[5]; };

__global__ __launch_bounds__(256)
void fill4cvt_kernel(Fill4 F, const int* __restrict__ off, const int* __restrict__ slot,
                     int* __restrict__ adj, int N,
                     const float* __restrict__ xA, const float* __restrict__ xB,
                     __half* __restrict__ xh, int nCvt) {
    int i = blockIdx.x * blockDim.x + threadIdx.x;
    if (i < F.cum[4]) {
        int e = 0;
#pragma unroll
        for (int t = 1; t < 4; t++) e += (i >= F.cum[t]);
        int k  = i - F.cum[e];
        int d  = __ldg(F.dst[e] + k);
        int sl = __ldg(slot + (size_t)e * EMAX + k);
        int o  = __ldg(off + (size_t)e * (N + 1) + d);
        adj[(size_t)e * EMAX + o + sl] = __ldg(F.src[e] + k);
    } else {
        int j = i - F.cum[4];
        if (j < nCvt) {                       // nCvt float4 chunks over [xA ; xB]
            int half_n = nCvt >> 1;
            float4 v = (j < half_n) ? __ldg((const float4*)xA + j)
                                    : __ldg((const float4*)xB + (j - half_n));
            __half2 h0 = __floats2half2_rn(v.x, v.y);
            __half2 h1 = __floats2half2_rn(v.z, v.w);
            ((__half2*)xh)[2 * j]     = h0;
            ((__half2*)xh)[2 * j + 1] = h1;
        }
    }
}

// ---------------- CSR aggregation: 2 edges per warp, 16 lanes per row ------------
// fp16 gather, fp32 accumulate, fp16 store. blockIdx.y = etype.
__global__ __launch_bounds__(256)
void aggcsr_kernel(const __half* __restrict__ xh,      // [2N, DH] : [A rows; B rows]
                   const float* __restrict__ rs, const int* __restrict__ offA,
                   const int* __restrict__ adjA, __half* __restrict__ aggA, int nN) {
    int e    = blockIdx.y;
    int w    = (int)((blockIdx.x * blockDim.x + threadIdx.x) >> 5);
    int lane = threadIdx.x & 31;
    if (w >= nN) return;
    int half = lane >> 4;          // which edge of the pair
    int sub  = lane & 15;          // 16B segment within the row

    const __half* x     = xh + ((e < 2) ? 0 : (size_t)nN * DH);  // 0:aa 1:ab 2:ba 3:bb
    const float* rs_out = rs + (size_t)(2 * e) * nN;
    const float* rs_in  = rs + (size_t)(2 * e + 1) * nN;
    const int*   off    = offA + (size_t)e * (nN + 1);
    const int*   adj    = adjA + (size_t)e * EMAX;
    __half*      agg    = aggA + (size_t)e * nN * DH;

    int s0 = __ldg(off + w);
    int s1 = __ldg(off + w + 1);
    int niter = (s1 - s0 + 1) >> 1;

    float acc[8];
#pragma unroll
    for (int i = 0; i < 8; i++) acc[i] = 0.f;

    for (int it = 0; it < niter; it++) {
        int j = s0 + 2 * it + half;
        bool v = (j < s1);
        int   s  = v ? __ldg(adj + j)    : 0;     // same addr across 16 lanes -> bcast
        float sc = v ? __ldg(rs_out + s) : 0.f;
        uint4 raw = __ldg((const uint4*)(x + (size_t)s * DH) + sub);
        __half2 h0 = *(__half2*)&raw.x;
        __half2 h1 = *(__half2*)&raw.y;
        __half2 h2 = *(__half2*)&raw.z;
        __half2 h3 = *(__half2*)&raw.w;
        float2 f0 = __half22float2(h0);
        float2 f1 = __half22float2(h1);
        float2 f2 = __half22float2(h2);
        float2 f3 = __half22float2(h3);
        acc[0] += sc * f0.x;  acc[1] += sc * f0.y;
        acc[2] += sc * f1.x;  acc[3] += sc * f1.y;
        acc[4] += sc * f2.x;  acc[5] += sc * f2.y;
        acc[6] += sc * f3.x;  acc[7] += sc * f3.y;
    }

    // merge the two half-warps (same sub segment lives on lanes sub and sub+16)
#pragma unroll
    for (int i = 0; i < 8; i++)
        acc[i] += __shfl_xor_sync(0xffffffffu, acc[i], 16);

    if (half == 0) {
        float ri = __ldg(rs_in + w);
        __half2 q0 = __floats2half2_rn(acc[0] * ri, acc[1] * ri);
        __half2 q1 = __floats2half2_rn(acc[2] * ri, acc[3] * ri);
        __half2 q2 = __floats2half2_rn(acc[4] * ri, acc[5] * ri);
        __half2 q3 = __floats2half2_rn(acc[6] * ri, acc[7] * ri);
        uint4 pk;
        pk.x = *(unsigned*)&q0; pk.y = *(unsigned*)&q1;
        pk.z = *(unsigned*)&q2; pk.w = *(unsigned*)&q3;
        ((uint4*)(agg + (size_t)w * DH))[sub] = pk;
    }
}

// ---------------- fused pair-GEMM + LayerNorm; both dst ntypes in one launch ------
// blockIdx.y = g (dst ntype); passes use etypes g and g+2.  A is fp16, math fp32.
extern __shared__ float s_mem[];

__global__ __launch_bounds__(256, 1)
void gemm_pair_ln_kernel(const __half* __restrict__ agg, const float* __restrict__ Wl,
                         const float* __restrict__ bl,
                         const float* __restrict__ gamma_l, const float* __restrict__ beta_l,
                         float* __restrict__ outf, __half* __restrict__ outh,
                         int nrows, int act) {
    float* Ws = s_mem;                 // 128*128 floats = 64 KB
    float* As = s_mem + DH * DH;       // 128*132 floats = 66 KB

    int tid = threadIdx.x;
    int tx = tid & 15;
    int ty = tid >> 4;
    int row0 = blockIdx.x * BM;
    int g    = blockIdx.y;
    const size_t ND = (size_t)nrows * DH;

    float accF[8][8];
#pragma unroll
    for (int r = 0; r < 8; r++)
#pragma unroll
        for (int c = 0; c < 8; c++) accF[r][c] = 0.f;

#pragma unroll 1
    for (int pass = 0; pass < 2; pass++) {
        int e = g + 2 * pass;                       // etypes: dstA {0,2}, dstB {1,3}
        const __half* A  = agg + (size_t)e * ND;
        const float*  W  = Wl + (size_t)e * DH * DH;
        const float*  bb = bl + (size_t)e * DH;

        __syncthreads();
        {
            const float4* Wv  = (const float4*)W;
            float4*       Wsv = (float4*)Ws;
#pragma unroll
            for (int i = 0; i < 16; i++) Wsv[tid + i * 256] = __ldg(Wv + tid + i * 256);
        }
        // stage A tile (128x128 halfs -> fp32 smem): 2048 uint4 chunks of 8 halfs
#pragma unroll
        for (int i = 0; i < 8; i++) {
            int idx = tid + i * 256;
            int r   = idx >> 4;
            int c8  = idx & 15;
            int grow = row0 + r;
            uint4 raw = make_uint4(0u, 0u, 0u, 0u);
            if (grow < nrows) raw = __ldg((const uint4*)(A + (size_t)grow * DH) + c8);
            float2 f0 = __half22float2(*(__half2*)&raw.x);
            float2 f1 = __half22float2(*(__half2*)&raw.y);
            float2 f2 = __half22float2(*(__half2*)&raw.z);
            float2 f3 = __half22float2(*(__half2*)&raw.w);
            float* dstp = As + r * APITCH + c8 * 8;
            *((float4*)dstp)       = make_float4(f0.x, f0.y, f1.x, f1.y);
            *((float4*)(dstp + 4)) = make_float4(f2.x, f2.y, f3.x, f3.y);
        }
        __syncthreads();

        u64t acc2[8][4];
#pragma unroll
        for (int r = 0; r < 8; r++)
#pragma unroll
            for (int c = 0; c < 4; c++) acc2[r][c] = 0ull;

#pragma unroll 1
        for (int k = 0; k < DH; k += 4) {
            float4 a[8];
#pragma unroll
            for (int r = 0; r < 8; r++)
                a[r] = *(const float4*)(As + (ty * 8 + r) * APITCH + k);
#pragma unroll
            for (int kk = 0; kk < 4; kk++) {
                const ulonglong2* wrow = (const ulonglong2*)(Ws + (k + kk) * DH + tx * 8);
                ulonglong2 wv0 = wrow[0];
                ulonglong2 wv1 = wrow[1];
#pragma unroll
                for (int r = 0; r < 8; r++) {
                    float av = (kk == 0) ? a[r].x : (kk == 1) ? a[r].y
                             : (kk == 2) ? a[r].z : a[r].w;
                    u64t a2; PACK_DUP(a2, av);
                    FMA2(acc2[r][0], a2, wv0.x, acc2[r][0]);
                    FMA2(acc2[r][1], a2, wv0.y, acc2[r][1]);
                    FMA2(acc2[r][2], a2, wv1.x, acc2[r][2]);
                    FMA2(acc2[r][3], a2, wv1.y, acc2[r][3]);
                }
            }
        }

        float blv[8];
#pragma unroll
        for (int c = 0; c < 8; c++) blv[c] = __ldg(bb + tx * 8 + c);
#pragma unroll
        for (int r = 0; r < 8; r++)
#pragma unroll
            for (int c = 0; c < 4; c++) {
                float lo, hi;
                UNPACK2(lo, hi, acc2[r][c]);
                float v0 = lo + blv[2 * c];
                float v1 = hi + blv[2 * c + 1];
                if (act) { v0 = fmaxf(v0, 0.f); v1 = fmaxf(v1, 0.f); }
                accF[r][2 * c]     += v0;
                accF[r][2 * c + 1] += v1;
            }
    }

    // ---- fused LayerNorm over each row (16 lanes x 8 cols = 128) ----
    const float* gamma = gamma_l + (size_t)g * DH;
    const float* beta  = beta_l  + (size_t)g * DH;
    float gl[8], be[8];
#pragma unroll
    for (int c = 0; c < 8; c++) {
        gl[c] = __ldg(gamma + tx * 8 + c);
        be[c] = __ldg(beta  + tx * 8 + c);
    }
#pragma unroll
    for (int r = 0; r < 8; r++) {
        float s = 0.f, sq = 0.f;
#pragma unroll
        for (int c = 0; c < 8; c++) {
            s  += accF[r][c];
            sq += accF[r][c] * accF[r][c];
        }
#pragma unroll
        for (int o = 8; o > 0; o >>= 1) {
            s  += __shfl_xor_sync(0xffffffffu, s,  o);
            sq += __shfl_xor_sync(0xffffffffu, sq, o);
        }
        float mean = s * (1.f / 128.f);
        float var  = sq * (1.f / 128.f) - mean * mean;
        float inv  = rsqrtf(var + 1e-5f);

        int grow = row0 + ty * 8 + r;
        if (grow < nrows) {
            float o0[8];
#pragma unroll
            for (int c = 0; c < 8; c++)
                o0[c] = (accF[r][c] - mean) * inv * gl[c] + be[c];
            size_t rowbase = (size_t)g * ND + (size_t)grow * DH + tx * 8;
            if (outh) {
                __half2 q0 = __floats2half2_rn(o0[0], o0[1]);
                __half2 q1 = __floats2half2_rn(o0[2], o0[3]);
                __half2 q2 = __floats2half2_rn(o0[4], o0[5]);
                __half2 q3 = __floats2half2_rn(o0[6], o0[7]);
                uint4 pk;
                pk.x = *(unsigned*)&q0; pk.y = *(unsigned*)&q1;
                pk.z = *(unsigned*)&q2; pk.w = *(unsigned*)&q3;
                *((uint4*)(outh + rowbase)) = pk;
            } else {
                float4 f0 = make_float4(o0[0], o0[1], o0[2], o0[3]);
                float4 f1 = make_float4(o0[4], o0[5], o0[6], o0[7]);
                *((float4*)(outf + rowbase))     = f0;
                *((float4*)(outf + rowbase + 4)) = f1;
            }
        }
    }
}

// ---------------- host orchestration ----------------
extern "C" void kernel_launch(void* const* d_in, const int* in_sizes, int n_in,
                              void* d_out, int out_size) {
    const float* x_A  = (const float*)d_in[0];
    const float* x_B  = (const float*)d_in[1];
    const float* W0   = (const float*)d_in[2];
    const float* b0   = (const float*)d_in[3];
    const float* W1   = (const float*)d_in[4];
    const float* b1   = (const float*)d_in[5];
    const float* ln_g = (const float*)d_in[6];
    const float* ln_b = (const float*)d_in[7];
    const int* eidx[8];
    int        esz[8];
    for (int i = 0; i < 8; i++) { eidx[i] = (const int*)d_in[8 + i]; esz[i] = in_sizes[8 + i]; }
    // order: src_aa, dst_aa, src_ab, dst_ab, src_ba, dst_ba, src_bb, dst_bb

    const int N = in_sizes[0] / DH;
    float* out = (float*)d_out;

    int *deg, *off, *slot, *adj; float *rs; __half *aggh, *xh, *hh;
    cudaGetSymbolAddress((void**)&deg,  g_deg);
    cudaGetSymbolAddress((void**)&rs,   g_rs);
    cudaGetSymbolAddress((void**)&off,  g_off);
    cudaGetSymbolAddress((void**)&slot, g_slot);
    cudaGetSymbolAddress((void**)&adj,  g_adj);
    cudaGetSymbolAddress((void**)&aggh, g_aggh);
    cudaGetSymbolAddress((void**)&xh,   g_xh);
    cudaGetSymbolAddress((void**)&hh,   g_hh);

    const int smem_bytes = (DH * DH + BM * APITCH) * 4;
    cudaFuncSetAttribute(gemm_pair_ln_kernel, cudaFuncAttributeMaxDynamicSharedMemorySize, smem_bytes);

    // node 1: zero degree tables
    cudaMemsetAsync(deg, 0, 8 * (size_t)N * sizeof(int));
    // node 2: fused degree count + slot capture
    Ptr8 P; P.cum[0] = 0;
    for (int j = 0; j < 8; j++) { P.p[j] = eidx[j]; P.cum[j + 1] = P.cum[j] + esz[j]; }
    deg8_kernel<<<(P.cum[8] + 255) / 256, 256>>>(P, deg, slot, N);
    // node 3: CSR offsets + rsqrt degrees
    scan_rs_kernel<<<8, 1024>>>(deg, off, rs, N);
    // node 4: atomic-free CSR fill + x -> fp16 staging
    Fill4 F; F.cum[0] = 0;
    for (int e = 0; e < 4; e++) {
        F.src[e] = eidx[2 * e]; F.dst[e] = eidx[2 * e + 1];
        F.cum[e + 1] = F.cum[e] + esz[2 * e];
    }
    int nCvt = 2 * N * DH / 4;
    fill4cvt_kernel<<<(F.cum[4] + nCvt + 255) / 256, 256>>>(F, off, slot, adj, N,
                                                            x_A, x_B, xh, nCvt);

    dim3 agg_grid((N * 32 + 255) / 256, 4);
    dim3 gemm_grid((N + BM - 1) / BM, 2);

    // =================== layer 0 ===================
    aggcsr_kernel<<<agg_grid, 256>>>(xh, rs, off, adj, aggh, N);     // node 5 (profiled)
    gemm_pair_ln_kernel<<<gemm_grid, 256, smem_bytes>>>(
        aggh, W0, b0, ln_g + 0 * DH, ln_b + 0 * DH,
        nullptr, hh, N, /*act=*/1);

    // =================== layer 1 ===================
    aggcsr_kernel<<<agg_grid, 256>>>(hh, rs, off, adj, aggh, N);
    gemm_pair_ln_kernel<<<gemm_grid, 256, smem_bytes>>>(
        aggh, W1, b1, ln_g + 2 * DH, ln_b + 2 * DH,
        out, nullptr, N, /*act=*/0);
}

// round 8
// speedup vs baseline: 2.4270x; 1.3568x over previous
#include <cuda_runtime.h>
#include <cuda_fp16.h>
#include <cstdint>

#define NMAX 100000
#define EMAX 1600000
#define DH   128
#define BM   128
#define PA   136          // smem half pitch (A / W tiles)
#define PC   132          // smem float pitch (C tile)

// ---------------- scratch (static device globals; no allocation) ----------------
__device__ int    g_deg [8 * NMAX];
__device__ float  g_rs  [8 * NMAX];
__device__ int    g_off [4 * (NMAX + 1)];
__device__ int    g_slot[4 * EMAX];
__device__ int    g_adj [4 * EMAX];
__device__ __half g_aggh[4 * (size_t)NMAX * DH];    // aggregated features (fp16)
__device__ __half g_xs  [4 * (size_t)NMAX * DH];    // pre-scaled gather sources
__device__ __half g_whl [2 * 4 * 2 * DH * DH];      // W fp16 hi/lo [layer][e][part]

// ---------------- mma helpers ----------------
__device__ __forceinline__ uint32_t smem_u32(const void* p) {
    uint32_t a;
    asm("{ .reg .u64 t; cvta.to.shared.u64 t, %1; cvt.u32.u64 %0, t; }"
        : "=r"(a) : "l"(p));
    return a;
}
#define LDSM_X4(r, addr) \
    asm volatile("ldmatrix.sync.aligned.m8n8.x4.shared.b16 {%0,%1,%2,%3}, [%4];" \
        : "=r"((r)[0]), "=r"((r)[1]), "=r"((r)[2]), "=r"((r)[3]) : "r"(addr))
#define LDSM_X4T(r, addr) \
    asm volatile("ldmatrix.sync.aligned.m8n8.x4.trans.shared.b16 {%0,%1,%2,%3}, [%4];" \
        : "=r"((r)[0]), "=r"((r)[1]), "=r"((r)[2]), "=r"((r)[3]) : "r"(addr))
#define MMA16816(c, a, b) \
    asm volatile("mma.sync.aligned.m16n8k16.row.col.f32.f16.f16.f32 " \
        "{%0,%1,%2,%3}, {%4,%5,%6,%7}, {%8,%9}, {%0,%1,%2,%3};" \
        : "+f"((c)[0]), "+f"((c)[1]), "+f"((c)[2]), "+f"((c)[3]) \
        : "r"((a)[0]), "r"((a)[1]), "r"((a)[2]), "r"((a)[3]), "r"((b)[0]), "r"((b)[1]))

// ---------------- fused degree count; dst arrays also record edge slots ----------
struct Ptr8 { const int* p[8]; int cum[9]; };

__global__ __launch_bounds__(256)
void deg8_kernel(Ptr8 P, int* __restrict__ deg, int* __restrict__ slot, int N) {
    int i = blockIdx.x * blockDim.x + threadIdx.x;
    if (i >= P.cum[8]) return;
    int j = 0;
#pragma unroll
    for (int t = 1; t < 8; t++) j += (i >= P.cum[t]);
    int k = i - P.cum[j];
    int idx = __ldg(P.p[j] + k);
    int old = atomicAdd(&deg[j * N + idx], 1);
    if (j & 1) slot[(size_t)((j - 1) >> 1) * EMAX + k] = old;
}

// ---------------- scan (4 blocks) + rsqrt degrees (4 blocks) ----------------
__global__ __launch_bounds__(1024)
void scan_rs_kernel(const int* __restrict__ deg, int* __restrict__ off,
                    float* __restrict__ rs, int N) {
    int b = blockIdx.x;
    if (b >= 4) {
        int bb = b - 4;
        for (int i = bb * 2 * N + threadIdx.x; i < (bb + 1) * 2 * N; i += 1024)
            rs[i] = rsqrtf(fmaxf((float)__ldg(deg + i), 1.0f));
        return;
    }
    int e = b;
    const int* d = deg + (size_t)(2 * e + 1) * N;
    int* o = off + (size_t)e * (N + 1);

    int tid = threadIdx.x;
    int per = (N + 1023) / 1024;
    int s0 = tid * per;
    int s1 = min(s0 + per, N);

    int sum = 0;
    for (int i = s0; i < s1; i++) sum += d[i];

    __shared__ int wtot[32];
    int lane = tid & 31, wid = tid >> 5;
    int incl = sum;
#pragma unroll
    for (int ofs = 1; ofs < 32; ofs <<= 1) {
        int t = __shfl_up_sync(0xffffffffu, incl, ofs);
        if (lane >= ofs) incl += t;
    }
    if (lane == 31) wtot[wid] = incl;
    __syncthreads();
    if (wid == 0) {
        int w = wtot[lane];
        int wi = w;
#pragma unroll
        for (int ofs = 1; ofs < 32; ofs <<= 1) {
            int t = __shfl_up_sync(0xffffffffu, wi, ofs);
            if (lane >= ofs) wi += t;
        }
        wtot[lane] = wi - w;
    }
    __syncthreads();
    int excl = wtot[wid] + incl - sum;

    int running = excl;
    for (int i = s0; i < s1; i++) {
        o[i] = running;
        running += d[i];
    }
    if (s0 < N && s1 == N) o[N] = running;
}

// --- atomic-free CSR fill + pre-scaled fp16 staging of x + W hi/lo conversion ----
struct Fill4 { const int* src[4]; const int* dst[4]; int cum[5]; };

__global__ __launch_bounds__(256)
void fill_stage_kernel(Fill4 F, const int* __restrict__ off, const int* __restrict__ slot,
                       int* __restrict__ adj, int N,
                       const float* __restrict__ xA, const float* __restrict__ xB,
                       const float* __restrict__ W0, const float* __restrict__ W1,
                       const float* __restrict__ rs,
                       __half* __restrict__ xs, __half* __restrict__ whl,
                       int nXs, int nW) {
    int i = blockIdx.x * blockDim.x + threadIdx.x;
    if (i < F.cum[4]) {
        int e = 0;
#pragma unroll
        for (int t = 1; t < 4; t++) e += (i >= F.cum[t]);
        int k  = i - F.cum[e];
        int d  = __ldg(F.dst[e] + k);
        int sl = __ldg(slot + (size_t)e * EMAX + k);
        int o  = __ldg(off + (size_t)e * (N + 1) + d);
        adj[(size_t)e * EMAX + o + sl] = __ldg(F.src[e] + k);
        return;
    }
    int j = i - F.cum[4];
    if (j < nXs) {                        // xs_e[row] = x_src(e)[row] * rs_out_e[row]
        int perE = (N * DH) / 8;          // 8 elems per thread
        int e = j / perE;
        int t = j - e * perE;
        int row = t >> 4;                 // DH/8 = 16 chunks per row
        const float* x = (e < 2) ? xA : xB;
        float4 v0 = __ldg((const float4*)x + t * 2);
        float4 v1 = __ldg((const float4*)x + t * 2 + 1);
        float s = __ldg(rs + (size_t)(2 * e) * N + row);
        __half2 h0 = __floats2half2_rn(v0.x * s, v0.y * s);
        __half2 h1 = __floats2half2_rn(v0.z * s, v0.w * s);
        __half2 h2 = __floats2half2_rn(v1.x * s, v1.y * s);
        __half2 h3 = __floats2half2_rn(v1.z * s, v1.w * s);
        uint4 pk;
        pk.x = *(unsigned*)&h0; pk.y = *(unsigned*)&h1;
        pk.z = *(unsigned*)&h2; pk.w = *(unsigned*)&h3;
        ((uint4*)(xs + (size_t)e * N * DH))[t] = pk;
        return;
    }
    int jw = j - nXs;
    if (jw < nW) {                        // W -> fp16 hi/lo (4 floats per thread)
        int lay = jw >> 14;               // 16384 chunks per layer
        int jj  = jw & 16383;
        const float* W = lay ? W1 : W0;
        float4 v = __ldg((const float4*)W + jj);
        int e  = jj >> 12;                // 4096 chunks per etype
        int j4 = jj & 4095;
        float f[4] = { v.x, v.y, v.z, v.w };
        __half hi[4], lo[4];
#pragma unroll
        for (int q = 0; q < 4; q++) {
            hi[q] = __float2half_rn(f[q]);
            lo[q] = __float2half_rn(f[q] - __half2float(hi[q]));
        }
        __half* base = whl + (size_t)((lay * 4 + e) * 2) * (DH * DH);
        __half2 ph0 = __halves2half2(hi[0], hi[1]);
        __half2 ph1 = __halves2half2(hi[2], hi[3]);
        __half2 pl0 = __halves2half2(lo[0], lo[1]);
        __half2 pl1 = __halves2half2(lo[2], lo[3]);
        uint2 uh; uh.x = *(unsigned*)&ph0; uh.y = *(unsigned*)&ph1;
        uint2 ul; ul.x = *(unsigned*)&pl0; ul.y = *(unsigned*)&pl1;
        ((uint2*)base)[j4]                 = uh;
        ((uint2*)(base + DH * DH))[j4]     = ul;
    }
}

// ---------------- CSR aggregation: pre-scaled fp16 gather, fp32 accum -----------
__global__ __launch_bounds__(256)
void aggcsr_kernel(const __half* __restrict__ xsA, const float* __restrict__ rs,
                   const int* __restrict__ offA, const int* __restrict__ adjA,
                   __half* __restrict__ aggA, int nN) {
    int e    = blockIdx.y;
    int w    = (int)((blockIdx.x * blockDim.x + threadIdx.x) >> 5);
    int lane = threadIdx.x & 31;
    if (w >= nN) return;
    int half = lane >> 4;
    int sub  = lane & 15;

    const __half* x   = xsA + (size_t)e * nN * DH;
    const float* rs_in = rs + (size_t)(2 * e + 1) * nN;
    const int*   off  = offA + (size_t)e * (nN + 1);
    const int*   adj  = adjA + (size_t)e * EMAX;
    __half*      agg  = aggA + (size_t)e * nN * DH;

    int s0 = __ldg(off + w);
    int s1 = __ldg(off + w + 1);

    float acc[8];
#pragma unroll
    for (int i = 0; i < 8; i++) acc[i] = 0.f;

    int j = s0 + half;
    // unrolled x2: each half-warp walks edges j, j+2, j+4, ...
    for (; j + 2 < s1; j += 4) {
        int sA = __ldg(adj + j);
        int sB = __ldg(adj + j + 2);
        uint4 ra = __ldg((const uint4*)(x + (size_t)sA * DH) + sub);
        uint4 rb = __ldg((const uint4*)(x + (size_t)sB * DH) + sub);
        float2 f;
        f = __half22float2(*(__half2*)&ra.x); acc[0] += f.x; acc[1] += f.y;
        f = __half22float2(*(__half2*)&ra.y); acc[2] += f.x; acc[3] += f.y;
        f = __half22float2(*(__half2*)&ra.z); acc[4] += f.x; acc[5] += f.y;
        f = __half22float2(*(__half2*)&ra.w); acc[6] += f.x; acc[7] += f.y;
        f = __half22float2(*(__half2*)&rb.x); acc[0] += f.x; acc[1] += f.y;
        f = __half22float2(*(__half2*)&rb.y); acc[2] += f.x; acc[3] += f.y;
        f = __half22float2(*(__half2*)&rb.z); acc[4] += f.x; acc[5] += f.y;
        f = __half22float2(*(__half2*)&rb.w); acc[6] += f.x; acc[7] += f.y;
    }
    if (j < s1) {
        int sA = __ldg(adj + j);
        uint4 ra = __ldg((const uint4*)(x + (size_t)sA * DH) + sub);
        float2 f;
        f = __half22float2(*(__half2*)&ra.x); acc[0] += f.x; acc[1] += f.y;
        f = __half22float2(*(__half2*)&ra.y); acc[2] += f.x; acc[3] += f.y;
        f = __half22float2(*(__half2*)&ra.z); acc[4] += f.x; acc[5] += f.y;
        f = __half22float2(*(__half2*)&ra.w); acc[6] += f.x; acc[7] += f.y;
    }

#pragma unroll
    for (int i = 0; i < 8; i++)
        acc[i] += __shfl_xor_sync(0xffffffffu, acc[i], 16);

    if (half == 0) {
        float ri = __ldg(rs_in + w);
        __half2 q0 = __floats2half2_rn(acc[0] * ri, acc[1] * ri);
        __half2 q1 = __floats2half2_rn(acc[2] * ri, acc[3] * ri);
        __half2 q2 = __floats2half2_rn(acc[4] * ri, acc[5] * ri);
        __half2 q3 = __floats2half2_rn(acc[6] * ri, acc[7] * ri);
        uint4 pk;
        pk.x = *(unsigned*)&q0; pk.y = *(unsigned*)&q1;
        pk.z = *(unsigned*)&q2; pk.w = *(unsigned*)&q3;
        ((uint4*)(agg + (size_t)w * DH))[sub] = pk;
    }
}

// ---------------- tensor-core pair-GEMM + LN epilogue ----------------------------
// blockIdx.y = g (dst ntype); passes e = g, g+2. A fp16; W = fp16 hi + fp16 lo.
// layer 0: writes TWO fp16 copies into xs (scaled by rs_out of etypes 2g, 2g+1).
// layer 1: writes fp32 to outf.
extern __shared__ char gsm[];

__global__ __launch_bounds__(256)
void gemm_mma_ln_kernel(const __half* __restrict__ aggh, const __half* __restrict__ whl,
                        const float* __restrict__ bl,
                        const float* __restrict__ gamma_l, const float* __restrict__ beta_l,
                        const float* __restrict__ rs,
                        float* __restrict__ outf, __half* __restrict__ xs_out,
                        int nrows, int act, int layer) {
    __half* Ah  = (__half*)gsm;
    __half* Wh0 = (__half*)(gsm + 34816);
    __half* Wh1 = (__half*)(gsm + 69632);
    float*  Cs  = (float*)gsm;                  // aliases A/Wh0 after mainloop

    int tid = threadIdx.x, lane = tid & 31, wrp = tid >> 5;
    int wy = wrp >> 1, wx = wrp & 1;            // 4 row-warps x 2 col-warps
    int row0 = blockIdx.x * BM;
    int g    = blockIdx.y;
    const size_t ND = (size_t)nrows * DH;

    float accF[2][8][4];
#pragma unroll
    for (int m = 0; m < 2; m++)
#pragma unroll
        for (int nt = 0; nt < 8; nt++)
#pragma unroll
            for (int q = 0; q < 4; q++) accF[m][nt][q] = 0.f;

#pragma unroll 1
    for (int pass = 0; pass < 2; pass++) {
        int e = g + 2 * pass;
        const __half* A     = aggh + (size_t)e * ND;
        const __half* Whi_g = whl + (size_t)((layer * 4 + e) * 2) * (DH * DH);
        const __half* Wlo_g = Whi_g + DH * DH;
        const float*  bb    = bl + (size_t)e * DH;

        __syncthreads();
        // stage A (128x128 halfs, pitch PA)
#pragma unroll
        for (int i = 0; i < 8; i++) {
            int idx = tid + i * 256;
            int r = idx >> 4, c8 = idx & 15;
            int grow = row0 + r;
            uint4 v = make_uint4(0u, 0u, 0u, 0u);
            if (grow < nrows) v = __ldg((const uint4*)(A + (size_t)grow * DH) + c8);
            *(uint4*)(Ah + r * PA + c8 * 8) = v;
        }
        // stage W hi/lo
#pragma unroll
        for (int i = 0; i < 8; i++) {
            int idx = tid + i * 256;
            int r = idx >> 4, c8 = idx & 15;
            *(uint4*)(Wh0 + r * PA + c8 * 8) = __ldg((const uint4*)Whi_g + idx);
            *(uint4*)(Wh1 + r * PA + c8 * 8) = __ldg((const uint4*)Wlo_g + idx);
        }
        __syncthreads();

        float accP[2][8][4];
#pragma unroll
        for (int m = 0; m < 2; m++)
#pragma unroll
            for (int nt = 0; nt < 8; nt++)
#pragma unroll
                for (int q = 0; q < 4; q++) accP[m][nt][q] = 0.f;

        uint32_t aBase  = smem_u32(Ah)  + (uint32_t)(((wy * 32 + (lane & 15)) * PA + (lane >> 4) * 8) * 2);
        uint32_t bBase0 = smem_u32(Wh0) + (uint32_t)((((lane & 15)) * PA + wx * 64 + (lane >> 4) * 8) * 2);
        uint32_t bBase1 = smem_u32(Wh1) + (uint32_t)((((lane & 15)) * PA + wx * 64 + (lane >> 4) * 8) * 2);

#pragma unroll
        for (int ks = 0; ks < 8; ks++) {
            uint32_t a0[4], a1[4];
            LDSM_X4(a0, aBase + ks * 32);
            LDSM_X4(a1, aBase + 16 * PA * 2 + ks * 32);
#pragma unroll
            for (int np = 0; np < 4; np++) {
                uint32_t bh[4], blo[4];
                LDSM_X4T(bh,  bBase0 + ks * 16 * PA * 2 + np * 32);
                LDSM_X4T(blo, bBase1 + ks * 16 * PA * 2 + np * 32);
                MMA16816(accP[0][2 * np],     a0, bh);
                MMA16816(accP[0][2 * np],     a0, blo);
                MMA16816(accP[0][2 * np + 1], a0, bh + 2);
                MMA16816(accP[0][2 * np + 1], a0, blo + 2);
                MMA16816(accP[1][2 * np],     a1, bh);
                MMA16816(accP[1][2 * np],     a1, blo);
                MMA16816(accP[1][2 * np + 1], a1, bh + 2);
                MMA16816(accP[1][2 * np + 1], a1, blo + 2);
            }
        }

        // bias + relu + accumulate
#pragma unroll
        for (int nt = 0; nt < 8; nt++) {
            int col = wx * 64 + nt * 8 + (lane & 3) * 2;
            float b0v = __ldg(bb + col);
            float b1v = __ldg(bb + col + 1);
#pragma unroll
            for (int m = 0; m < 2; m++) {
                float v0 = accP[m][nt][0] + b0v;
                float v1 = accP[m][nt][1] + b1v;
                float v2 = accP[m][nt][2] + b0v;
                float v3 = accP[m][nt][3] + b1v;
                if (act) {
                    v0 = fmaxf(v0, 0.f); v1 = fmaxf(v1, 0.f);
                    v2 = fmaxf(v2, 0.f); v3 = fmaxf(v3, 0.f);
                }
                accF[m][nt][0] += v0; accF[m][nt][1] += v1;
                accF[m][nt][2] += v2; accF[m][nt][3] += v3;
            }
        }
    }

    __syncthreads();          // all smem reads done; C may alias A/W
    // dump fragments to C smem
#pragma unroll
    for (int m = 0; m < 2; m++)
#pragma unroll
        for (int nt = 0; nt < 8; nt++) {
            int ra  = wy * 32 + m * 16 + (lane >> 2);
            int col = wx * 64 + nt * 8 + (lane & 3) * 2;
            Cs[ra * PC + col]           = accF[m][nt][0];
            Cs[ra * PC + col + 1]       = accF[m][nt][1];
            Cs[(ra + 8) * PC + col]     = accF[m][nt][2];
            Cs[(ra + 8) * PC + col + 1] = accF[m][nt][3];
        }
    __syncthreads();

    // LayerNorm: warp wrp handles rows [wrp*16, wrp*16+16)
    const float* gamma = gamma_l + (size_t)g * DH;
    const float* beta  = beta_l  + (size_t)g * DH;
    float4 gv = __ldg((const float4*)gamma + lane);
    float4 bv = __ldg((const float4*)beta + lane);

    for (int r = 0; r < 16; r++) {
        int row = wrp * 16 + r;
        float4 v = *(float4*)(Cs + row * PC + lane * 4);
        float s  = v.x + v.y + v.z + v.w;
        float sq = v.x * v.x + v.y * v.y + v.z * v.z + v.w * v.w;
#pragma unroll
        for (int o = 16; o > 0; o >>= 1) {
            s  += __shfl_xor_sync(0xffffffffu, s,  o);
            sq += __shfl_xor_sync(0xffffffffu, sq, o);
        }
        float mean = s * (1.f / 128.f);
        float var  = sq * (1.f / 128.f) - mean * mean;
        float inv  = rsqrtf(var + 1e-5f);

        int grow = row0 + row;
        if (grow < nrows) {
            float o0 = (v.x - mean) * inv * gv.x + bv.x;
            float o1 = (v.y - mean) * inv * gv.y + bv.y;
            float o2 = (v.z - mean) * inv * gv.z + bv.z;
            float o3 = (v.w - mean) * inv * gv.w + bv.w;
            if (xs_out) {
                float rA = __ldg(rs + (size_t)(4 * g) * nrows + grow);
                float rB = __ldg(rs + (size_t)(4 * g + 2) * nrows + grow);
                __half2 p0 = __floats2half2_rn(o0 * rA, o1 * rA);
                __half2 p1 = __floats2half2_rn(o2 * rA, o3 * rA);
                uint2 u0; u0.x = *(unsigned*)&p0; u0.y = *(unsigned*)&p1;
                *((uint2*)(xs_out + (size_t)(2 * g) * ND + (size_t)grow * DH + lane * 4)) = u0;
                __half2 p2 = __floats2half2_rn(o0 * rB, o1 * rB);
                __half2 p3 = __floats2half2_rn(o2 * rB, o3 * rB);
                uint2 u1; u1.x = *(unsigned*)&p2; u1.y = *(unsigned*)&p3;
                *((uint2*)(xs_out + (size_t)(2 * g + 1) * ND + (size_t)grow * DH + lane * 4)) = u1;
            } else {
                *((float4*)(outf + (size_t)g * ND + (size_t)grow * DH + lane * 4)) =
                    make_float4(o0, o1, o2, o3);
            }
        }
    }
}

// ---------------- host orchestration ----------------
extern "C" void kernel_launch(void* const* d_in, const int* in_sizes, int n_in,
                              void* d_out, int out_size) {
    const float* x_A  = (const float*)d_in[0];
    const float* x_B  = (const float*)d_in[1];
    const float* W0   = (const float*)d_in[2];
    const float* b0   = (const float*)d_in[3];
    const float* W1   = (const float*)d_in[4];
    const float* b1   = (const float*)d_in[5];
    const float* ln_g = (const float*)d_in[6];
    const float* ln_b = (const float*)d_in[7];
    const int* eidx[8];
    int        esz[8];
    for (int i = 0; i < 8; i++) { eidx[i] = (const int*)d_in[8 + i]; esz[i] = in_sizes[8 + i]; }
    // order: src_aa, dst_aa, src_ab, dst_ab, src_ba, dst_ba, src_bb, dst_bb

    const int N = in_sizes[0] / DH;
    float* out = (float*)d_out;

    int *deg, *off, *slot, *adj; float *rs; __half *aggh, *xs, *whl;
    cudaGetSymbolAddress((void**)&deg,  g_deg);
    cudaGetSymbolAddress((void**)&rs,   g_rs);
    cudaGetSymbolAddress((void**)&off,  g_off);
    cudaGetSymbolAddress((void**)&slot, g_slot);
    cudaGetSymbolAddress((void**)&adj,  g_adj);
    cudaGetSymbolAddress((void**)&aggh, g_aggh);
    cudaGetSymbolAddress((void**)&xs,   g_xs);
    cudaGetSymbolAddress((void**)&whl,  g_whl);

    const int gemm_smem = 104448;     // A(34816) + Whi(34816) + Wlo(34816); C aliases
    cudaFuncSetAttribute(gemm_mma_ln_kernel,
                         cudaFuncAttributeMaxDynamicSharedMemorySize, gemm_smem);

    // 1) zero degree tables
    cudaMemsetAsync(deg, 0, 8 * (size_t)N * sizeof(int));
    // 2) degree count + slot capture
    Ptr8 P; P.cum[0] = 0;
    for (int j = 0; j < 8; j++) { P.p[j] = eidx[j]; P.cum[j + 1] = P.cum[j] + esz[j]; }
    deg8_kernel<<<(P.cum[8] + 255) / 256, 256>>>(P, deg, slot, N);
    // 3) CSR offsets + rsqrt degrees
    scan_rs_kernel<<<8, 1024>>>(deg, off, rs, N);
    // 4) CSR fill + pre-scaled x staging + W hi/lo conversion
    Fill4 F; F.cum[0] = 0;
    for (int e = 0; e < 4; e++) {
        F.src[e] = eidx[2 * e]; F.dst[e] = eidx[2 * e + 1];
        F.cum[e + 1] = F.cum[e] + esz[2 * e];
    }
    int nXs = 4 * (N * DH / 8);
    int nW  = 2 * 4 * DH * DH / 4;
    fill_stage_kernel<<<(F.cum[4] + nXs + nW + 255) / 256, 256>>>(
        F, off, slot, adj, N, x_A, x_B, W0, W1, rs, xs, whl, nXs, nW);

    dim3 agg_grid((N * 32 + 255) / 256, 4);
    dim3 gemm_grid((N + BM - 1) / BM, 2);

    // =================== layer 0 ===================
    aggcsr_kernel<<<agg_grid, 256>>>(xs, rs, off, adj, aggh, N);
    gemm_mma_ln_kernel<<<gemm_grid, 256, gemm_smem>>>(
        aggh, whl, b0, ln_g + 0, ln_b + 0, rs,
        nullptr, xs, N, /*act=*/1, /*layer=*/0);

    // =================== layer 1 ===================
    aggcsr_kernel<<<agg_grid, 256>>>(xs, rs, off, adj, aggh, N);
    gemm_mma_ln_kernel<<<gemm_grid, 256, gemm_smem>>>(
        aggh, whl, b1, ln_g + 2 * DH, ln_b + 2 * DH, rs,
        out, nullptr, N, /*act=*/0, /*layer=*/1);
}